// round 8
// baseline (speedup 1.0000x reference)
#include <cuda_runtime.h>
#include <cuda_bf16.h>
#include <stdint.h>

#define SQ   4096
#define DIM  1024
#define NH   16
#define HD   64
#define QT   64    // queries per attention block (halved: 2 CTAs/SM)
#define KT   64

// Scratch (allocation-free rule: __device__ globals)
__device__ __nv_bfloat16 g_xh[SQ * DIM],  g_xl[SQ * DIM];
__device__ __nv_bfloat16 g_wqh[DIM * DIM], g_wql[DIM * DIM];
__device__ __nv_bfloat16 g_wkh[DIM * DIM], g_wkl[DIM * DIM];
__device__ __nv_bfloat16 g_wvh[DIM * DIM], g_wvl[DIM * DIM];
__device__ __nv_bfloat16 g_woh[DIM * DIM], g_wol[DIM * DIM];
__device__ __nv_bfloat16 g_qh[SQ * DIM], g_ql[SQ * DIM];
__device__ __nv_bfloat16 g_kh[SQ * DIM], g_kl[SQ * DIM];
__device__ __nv_bfloat16 g_vh[SQ * DIM], g_vl[SQ * DIM];
__device__ __nv_bfloat16 g_oh[SQ * DIM], g_ol[SQ * DIM];

// ---------------------------------------------------------------------------
// Helpers
// ---------------------------------------------------------------------------
__device__ __forceinline__ uint32_t smem_u32(const void* p) {
    uint32_t a;
    asm("{ .reg .u64 t; cvta.to.shared.u64 t, %1; cvt.u32.u64 %0, t; }"
        : "=r"(a) : "l"(p));
    return a;
}
#define SWZ(off)  ((off) ^ (((off) >> 3) & 0x70))   // 128B rows
#define SW64(off) ((off) ^ (((off) >> 3) & 0x30))   // 64B rows

#define CP16(dst, src) \
    asm volatile("cp.async.cg.shared.global [%0], [%1], 16;" :: "r"(dst), "l"(src))
#define CP_COMMIT() asm volatile("cp.async.commit_group;" ::: "memory")
#define CP_WAIT1()  asm volatile("cp.async.wait_group 1;" ::: "memory")

__device__ __forceinline__ void mma_bf16(float* d, const uint32_t* a,
                                         uint32_t b0, uint32_t b1) {
    asm volatile(
        "mma.sync.aligned.m16n8k16.row.col.f32.bf16.bf16.f32 "
        "{%0,%1,%2,%3}, {%4,%5,%6,%7}, {%8,%9}, {%0,%1,%2,%3};"
        : "+f"(d[0]), "+f"(d[1]), "+f"(d[2]), "+f"(d[3])
        : "r"(a[0]), "r"(a[1]), "r"(a[2]), "r"(a[3]), "r"(b0), "r"(b1));
}
__device__ __forceinline__ void ldm_x4(uint32_t* r, uint32_t addr) {
    asm volatile("ldmatrix.sync.aligned.m8n8.x4.shared.b16 {%0,%1,%2,%3}, [%4];"
        : "=r"(r[0]), "=r"(r[1]), "=r"(r[2]), "=r"(r[3]) : "r"(addr));
}
__device__ __forceinline__ void ldm_x4_t(uint32_t* r, uint32_t addr) {
    asm volatile("ldmatrix.sync.aligned.m8n8.x4.trans.shared.b16 {%0,%1,%2,%3}, [%4];"
        : "=r"(r[0]), "=r"(r[1]), "=r"(r[2]), "=r"(r[3]) : "r"(addr));
}

// ---------------------------------------------------------------------------
// fp32 -> bf16 hi/lo split (elementwise)
// ---------------------------------------------------------------------------
__global__ void __launch_bounds__(256) split32(
    const float* __restrict__ in, __nv_bfloat16* __restrict__ hi,
    __nv_bfloat16* __restrict__ lo, int n)
{
    int i = (blockIdx.x * 256 + threadIdx.x) * 4;
    if (i >= n) return;
    float4 f = *(const float4*)(in + i);
    __nv_bfloat162 h0 = __floats2bfloat162_rn(f.x, f.y);
    __nv_bfloat162 h1 = __floats2bfloat162_rn(f.z, f.w);
    __nv_bfloat162 l0 = __floats2bfloat162_rn(f.x - __bfloat162float(h0.x),
                                              f.y - __bfloat162float(h0.y));
    __nv_bfloat162 l1 = __floats2bfloat162_rn(f.z - __bfloat162float(h1.x),
                                              f.w - __bfloat162float(h1.y));
    uint2 hv = {*(uint32_t*)&h0, *(uint32_t*)&h1};
    uint2 lv = {*(uint32_t*)&l0, *(uint32_t*)&l1};
    *(uint2*)(hi + i) = hv;
    *(uint2*)(lo + i) = lv;
}

// ---------------------------------------------------------------------------
// Split-bf16 tensor GEMM: C[M,N] = A @ B^T + bias, M=SQ, N=K=DIM.
// BM=128, BN=128, k-step 32, cp.async double buffer (2 x 32KB).
// 256 threads = 8 warps (2m x 4n), warp tile 64x32.
// SPLIT_OUT: 0 -> fp32 C; 1 -> bf16 hi/lo pair.
// ---------------------------------------------------------------------------
#define GS_STAGE 32768

template<int SPLIT_OUT>
__global__ void __launch_bounds__(256, 1) gemm_mma(
    const __nv_bfloat16* __restrict__ Agh, const __nv_bfloat16* __restrict__ Agl,
    const __nv_bfloat16* __restrict__ Bgh, const __nv_bfloat16* __restrict__ Bgl,
    const float* __restrict__ bias, float* __restrict__ C,
    __nv_bfloat16* __restrict__ Chi, __nv_bfloat16* __restrict__ Clo)
{
    extern __shared__ char sm[];
    const uint32_t smb = smem_u32(sm);
    const int tid = threadIdx.x, lane = tid & 31, warp = tid >> 5;
    const int bm = blockIdx.y * 128, bn = blockIdx.x * 128;
    const int wm = (warp >> 2) * 64, wn = (warp & 3) * 32;

    // loader role: buf 0:Ah 1:Al 2:Bh 3:Bl; 64 threads per buf, 2 rows each
    const int buf = tid >> 6, lrow = tid & 63;
    const __nv_bfloat16* gp[4] = {Agh, Agl, Bgh, Bgl};
    const int rbase = (buf < 2 ? bm : bn) + lrow;
    const __nv_bfloat16* src0 = gp[buf] + (size_t)rbase * DIM;
    const __nv_bfloat16* src1 = gp[buf] + (size_t)(rbase + 64) * DIM;

    float acc[4][4][4];
#pragma unroll
    for (int a = 0; a < 4; a++)
#pragma unroll
        for (int b = 0; b < 4; b++)
#pragma unroll
            for (int c = 0; c < 4; c++) acc[a][b][c] = 0.f;

    // prologue: stage 0
    {
        uint32_t db = smb + buf * 8192;
#pragma unroll
        for (int i = 0; i < 4; i++) {
            CP16(db + SW64((uint32_t)(lrow * 64 + i * 16)),        src0 + i * 8);
            CP16(db + SW64((uint32_t)((lrow + 64) * 64 + i * 16)), src1 + i * 8);
        }
    }
    CP_COMMIT();

    for (int kt = 0; kt < 32; kt++) {
        if (kt + 1 < 32) {
            uint32_t db = smb + ((kt + 1) & 1) * GS_STAGE + buf * 8192;
            const __nv_bfloat16* s0 = src0 + (kt + 1) * 32;
            const __nv_bfloat16* s1 = src1 + (kt + 1) * 32;
#pragma unroll
            for (int i = 0; i < 4; i++) {
                CP16(db + SW64((uint32_t)(lrow * 64 + i * 16)),        s0 + i * 8);
                CP16(db + SW64((uint32_t)((lrow + 64) * 64 + i * 16)), s1 + i * 8);
            }
        }
        CP_COMMIT();
        CP_WAIT1();
        __syncthreads();

        const uint32_t sb = smb + (kt & 1) * GS_STAGE;
#pragma unroll
        for (int kk = 0; kk < 2; kk++) {
            uint32_t ah[4][4], al[4][4];
#pragma unroll
            for (int mf = 0; mf < 4; mf++) {
                uint32_t off = SW64((uint32_t)((wm + mf * 16 + (lane & 15)) * 64
                                    + kk * 32 + (lane >> 4) * 16));
                ldm_x4(ah[mf], sb + off);
                ldm_x4(al[mf], sb + 8192 + off);
            }
#pragma unroll
            for (int nf = 0; nf < 2; nf++) {
                uint32_t bh[4], bl[4];
                uint32_t off = SW64((uint32_t)((wn + nf * 16 + ((lane >> 4) << 3)
                                    + (lane & 7)) * 64 + kk * 32
                                    + ((lane >> 3) & 1) * 16));
                ldm_x4(bh, sb + 16384 + off);
                ldm_x4(bl, sb + 24576 + off);
#pragma unroll
                for (int mf = 0; mf < 4; mf++) {
                    mma_bf16(acc[mf][2*nf],   ah[mf], bh[0], bh[1]);
                    mma_bf16(acc[mf][2*nf],   ah[mf], bl[0], bl[1]);
                    mma_bf16(acc[mf][2*nf],   al[mf], bh[0], bh[1]);
                    mma_bf16(acc[mf][2*nf+1], ah[mf], bh[2], bh[3]);
                    mma_bf16(acc[mf][2*nf+1], ah[mf], bl[2], bl[3]);
                    mma_bf16(acc[mf][2*nf+1], al[mf], bh[2], bh[3]);
                }
            }
        }
        __syncthreads();
    }

    // epilogue
#pragma unroll
    for (int mf = 0; mf < 4; mf++) {
        int r0 = bm + wm + mf * 16 + (lane >> 2);
#pragma unroll
        for (int nf8 = 0; nf8 < 4; nf8++) {
            int c = bn + wn + nf8 * 8 + (lane & 3) * 2;
            float b0 = bias[c], b1 = bias[c + 1];
            float v0 = acc[mf][nf8][0] + b0, v1 = acc[mf][nf8][1] + b1;
            float v2 = acc[mf][nf8][2] + b0, v3 = acc[mf][nf8][3] + b1;
            if (SPLIT_OUT) {
                __nv_bfloat162 h0 = __floats2bfloat162_rn(v0, v1);
                __nv_bfloat162 l0 = __floats2bfloat162_rn(v0 - __bfloat162float(h0.x),
                                                          v1 - __bfloat162float(h0.y));
                __nv_bfloat162 h1 = __floats2bfloat162_rn(v2, v3);
                __nv_bfloat162 l1 = __floats2bfloat162_rn(v2 - __bfloat162float(h1.x),
                                                          v3 - __bfloat162float(h1.y));
                *(uint32_t*)&Chi[(size_t)r0 * DIM + c]       = *(uint32_t*)&h0;
                *(uint32_t*)&Clo[(size_t)r0 * DIM + c]       = *(uint32_t*)&l0;
                *(uint32_t*)&Chi[(size_t)(r0 + 8) * DIM + c] = *(uint32_t*)&h1;
                *(uint32_t*)&Clo[(size_t)(r0 + 8) * DIM + c] = *(uint32_t*)&l1;
            } else {
                float2 w0 = {v0, v1}, w1 = {v2, v3};
                *(float2*)&C[(size_t)r0 * DIM + c]       = w0;
                *(float2*)&C[(size_t)(r0 + 8) * DIM + c] = w1;
            }
        }
    }
}

// ---------------------------------------------------------------------------
// Attention: mma.sync split bf16, fixed-shift softmax, cp.async double-buffer.
// QT=64, 128 threads (4 warps), 2 CTAs/SM for cross-CTA overlap.
// smem: Q 16KB (Qh/Ql) + 2 KV stages x 32KB = 80KB.
// ---------------------------------------------------------------------------
#define SM_Q0   0
#define SM_KV0  16384
#define ATT_SMEM 81920

__global__ void __launch_bounds__(128, 2) attn_mma(
    const __nv_bfloat16* __restrict__ Qh, const __nv_bfloat16* __restrict__ Ql,
    const __nv_bfloat16* __restrict__ Kh, const __nv_bfloat16* __restrict__ Kl,
    const __nv_bfloat16* __restrict__ Vh, const __nv_bfloat16* __restrict__ Vl,
    const float* __restrict__ phase,
    __nv_bfloat16* __restrict__ Oh, __nv_bfloat16* __restrict__ Ol)
{
    extern __shared__ char sm[];
    const uint32_t smb = smem_u32(sm);
    const int tid  = threadIdx.x;
    const int lane = tid & 31;
    const int warp = tid >> 5;           // 0..3
    const int h  = blockIdx.y;
    const int qb = blockIdx.x * QT;
    const int m0 = warp * 16;
    const float ph = phase[h];

    // KV loader role: buf 0:Kh 1:Kl 2:Vh 3:Vl; 32 threads/buf, 2 rows each
    const int buf = tid >> 5, lrow = tid & 31;
    const __nv_bfloat16* gkv[4] = {Kh, Kl, Vh, Vl};
    const __nv_bfloat16* kvsrc0 = gkv[buf] + (size_t)lrow * DIM + h * HD;
    const __nv_bfloat16* kvsrc1 = gkv[buf] + (size_t)(lrow + 32) * DIM + h * HD;

    // prologue: prefetch KV tile 0
    {
        uint32_t db = smb + SM_KV0 + buf * 8192;
#pragma unroll
        for (int i = 0; i < 8; i++) {
            CP16(db + SWZ((uint32_t)(lrow * 128 + i * 16)),        kvsrc0 + i * 8);
            CP16(db + SWZ((uint32_t)((lrow + 32) * 128 + i * 16)), kvsrc1 + i * 8);
        }
    }
    CP_COMMIT();

    // stage Q hi/lo tiles (64 rows x 128B each buf)
    {
        const int qbuf = tid >> 6;          // 0: hi, 1: lo
        const int row = tid & 63;
        const __nv_bfloat16* src = (qbuf ? Ql : Qh) + (size_t)(qb + row) * DIM + h * HD;
        char* dst = sm + SM_Q0 + qbuf * 8192;
        const uint4* s4 = (const uint4*)src;
#pragma unroll
        for (int i = 0; i < 8; i++)
            *(uint4*)(dst + SWZ((uint32_t)(row * 128 + i * 16))) = s4[i];
    }
    __syncthreads();

    // preload Q A-fragments (warp owns rows m0..m0+15)
    uint32_t qfh[4][4], qfl[4][4];
    {
        const uint32_t qrow = (uint32_t)(m0 + (lane & 15));
        const uint32_t qcol = (uint32_t)((lane >> 4) * 16);
#pragma unroll
        for (int kk = 0; kk < 4; kk++) {
            uint32_t off = SWZ(qrow * 128 + kk * 32 + qcol);
            ldm_x4(qfh[kk], smb + SM_Q0 + off);
            ldm_x4(qfl[kk], smb + SM_Q0 + 8192 + off);
        }
    }

    const uint32_t krow = (uint32_t)(((lane >> 4) << 3) + (lane & 7));
    const uint32_t kcol = (uint32_t)(((lane >> 3) & 1) * 16);
    const uint32_t vrow = (uint32_t)((((lane >> 3) & 1) << 3) + (lane & 7));
    const uint32_t vcol = (uint32_t)((lane >> 4) * 16);

    float o[8][4];
#pragma unroll
    for (int n = 0; n < 8; n++)
#pragma unroll
        for (int e = 0; e < 4; e++) o[n][e] = 0.f;
    float lsum0 = 0.f, lsum8 = 0.f;

    for (int t = 0; t < SQ / KT; t++) {
        // prefetch next KV tile into other stage
        if (t + 1 < SQ / KT) {
            uint32_t db = smb + SM_KV0 + ((t + 1) & 1) * 32768 + buf * 8192;
            const __nv_bfloat16* s0 = kvsrc0 + (size_t)(t + 1) * KT * DIM;
            const __nv_bfloat16* s1 = kvsrc1 + (size_t)(t + 1) * KT * DIM;
#pragma unroll
            for (int i = 0; i < 8; i++) {
                CP16(db + SWZ((uint32_t)(lrow * 128 + i * 16)),        s0 + i * 8);
                CP16(db + SWZ((uint32_t)((lrow + 32) * 128 + i * 16)), s1 + i * 8);
            }
        }
        CP_COMMIT();
        CP_WAIT1();
        __syncthreads();

        const uint32_t kvb = smb + SM_KV0 + (t & 1) * 32768;

        // ---- S = Q K^T (hh + hl + lh) ----
        float s[8][4];
#pragma unroll
        for (int n = 0; n < 8; n++)
#pragma unroll
            for (int e = 0; e < 4; e++) s[n][e] = 0.f;

#pragma unroll
        for (int kk = 0; kk < 4; kk++) {
#pragma unroll
            for (int np = 0; np < 4; np++) {
                uint32_t bh[4], bl[4];
                uint32_t off = SWZ((np * 16 + krow) * 128 + kk * 32 + kcol);
                ldm_x4(bh, kvb + off);
                ldm_x4(bl, kvb + 8192 + off);
                mma_bf16(s[2*np],   qfh[kk], bh[0], bh[1]);
                mma_bf16(s[2*np],   qfh[kk], bl[0], bl[1]);
                mma_bf16(s[2*np],   qfl[kk], bh[0], bh[1]);
                mma_bf16(s[2*np+1], qfh[kk], bh[2], bh[3]);
                mma_bf16(s[2*np+1], qfh[kk], bl[2], bl[3]);
                mma_bf16(s[2*np+1], qfl[kk], bh[2], bh[3]);
            }
        }

        // ---- modulation + exp(. - 16) ----
#pragma unroll
        for (int n = 0; n < 8; n++) {
#pragma unroll
            for (int e = 0; e < 4; e++) {
                float sc = s[n][e] * 0.125f;
                float m  = sc * (1.f + 0.1f * __cosf(ph * sc));
                s[n][e]  = __expf(m - 16.f);
            }
            lsum0 += s[n][0] + s[n][1];
            lsum8 += s[n][2] + s[n][3];
        }

        // ---- O += P V ----
#pragma unroll
        for (int kk = 0; kk < 4; kk++) {
            const int t0 = 2 * kk, t1 = 2 * kk + 1;
            uint32_t ah[4], al[4];
            const float* pv[4] = {&s[t0][0], &s[t0][2], &s[t1][0], &s[t1][2]};
#pragma unroll
            for (int q = 0; q < 4; q++) {
                float p0 = pv[q][0], p1 = pv[q][1];
                __nv_bfloat162 hp = __floats2bfloat162_rn(p0, p1);
                float r0 = p0 - __bfloat162float(hp.x);
                float r1 = p1 - __bfloat162float(hp.y);
                __nv_bfloat162 lp = __floats2bfloat162_rn(r0, r1);
                ah[q] = *(uint32_t*)&hp;
                al[q] = *(uint32_t*)&lp;
            }
#pragma unroll
            for (int dp = 0; dp < 4; dp++) {
                uint32_t bh[4], bl[4];
                uint32_t off = SWZ((kk * 16 + vrow) * 128 + dp * 32 + vcol);
                ldm_x4_t(bh, kvb + 16384 + off);
                ldm_x4_t(bl, kvb + 24576 + off);
                mma_bf16(o[2*dp],   ah, bh[0], bh[1]);
                mma_bf16(o[2*dp],   ah, bl[0], bl[1]);
                mma_bf16(o[2*dp],   al, bh[0], bh[1]);
                mma_bf16(o[2*dp+1], ah, bh[2], bh[3]);
                mma_bf16(o[2*dp+1], ah, bl[2], bl[3]);
                mma_bf16(o[2*dp+1], al, bh[2], bh[3]);
            }
        }
        __syncthreads();
    }

    // ---- finalize: l-reduce, scale, write split bf16 ----
    lsum0 += __shfl_xor_sync(0xffffffffu, lsum0, 1);
    lsum0 += __shfl_xor_sync(0xffffffffu, lsum0, 2);
    lsum8 += __shfl_xor_sync(0xffffffffu, lsum8, 1);
    lsum8 += __shfl_xor_sync(0xffffffffu, lsum8, 2);
    const float inv0 = 1.f / lsum0;
    const float inv8 = 1.f / lsum8;

    const int row0 = qb + m0 + (lane >> 2);
    const int colb = h * HD + (lane & 3) * 2;
#pragma unroll
    for (int n = 0; n < 8; n++) {
        float a0 = o[n][0] * inv0, a1 = o[n][1] * inv0;
        float b0 = o[n][2] * inv8, b1 = o[n][3] * inv8;
        __nv_bfloat162 h0 = __floats2bfloat162_rn(a0, a1);
        __nv_bfloat162 l0 = __floats2bfloat162_rn(a0 - __bfloat162float(h0.x),
                                                  a1 - __bfloat162float(h0.y));
        __nv_bfloat162 h1 = __floats2bfloat162_rn(b0, b1);
        __nv_bfloat162 l1 = __floats2bfloat162_rn(b0 - __bfloat162float(h1.x),
                                                  b1 - __bfloat162float(h1.y));
        size_t i0 = (size_t)row0 * DIM + colb + n * 8;
        size_t i1 = (size_t)(row0 + 8) * DIM + colb + n * 8;
        *(uint32_t*)&Oh[i0] = *(uint32_t*)&h0;
        *(uint32_t*)&Ol[i0] = *(uint32_t*)&l0;
        *(uint32_t*)&Oh[i1] = *(uint32_t*)&h1;
        *(uint32_t*)&Ol[i1] = *(uint32_t*)&l1;
    }
}

// ---------------------------------------------------------------------------
extern "C" void kernel_launch(void* const* d_in, const int* in_sizes, int n_in,
                              void* d_out, int out_size)
{
    const float* x     = (const float*)d_in[0];
    const float* wq    = (const float*)d_in[1];
    const float* bq    = (const float*)d_in[2];
    const float* wk    = (const float*)d_in[3];
    const float* bk    = (const float*)d_in[4];
    const float* wv    = (const float*)d_in[5];
    const float* bv    = (const float*)d_in[6];
    const float* wo    = (const float*)d_in[7];
    const float* bo    = (const float*)d_in[8];
    const float* phase = (const float*)d_in[9];
    float* out = (float*)d_out;

    __nv_bfloat16 *xh, *xl, *wqh, *wql, *wkh, *wkl, *wvh, *wvl, *woh, *wol;
    __nv_bfloat16 *qh, *ql, *kh, *kl, *vh, *vl, *oh, *ol;
    cudaGetSymbolAddress((void**)&xh,  g_xh);  cudaGetSymbolAddress((void**)&xl,  g_xl);
    cudaGetSymbolAddress((void**)&wqh, g_wqh); cudaGetSymbolAddress((void**)&wql, g_wql);
    cudaGetSymbolAddress((void**)&wkh, g_wkh); cudaGetSymbolAddress((void**)&wkl, g_wkl);
    cudaGetSymbolAddress((void**)&wvh, g_wvh); cudaGetSymbolAddress((void**)&wvl, g_wvl);
    cudaGetSymbolAddress((void**)&woh, g_woh); cudaGetSymbolAddress((void**)&wol, g_wol);
    cudaGetSymbolAddress((void**)&qh, g_qh); cudaGetSymbolAddress((void**)&ql, g_ql);
    cudaGetSymbolAddress((void**)&kh, g_kh); cudaGetSymbolAddress((void**)&kl, g_kl);
    cudaGetSymbolAddress((void**)&vh, g_vh); cudaGetSymbolAddress((void**)&vl, g_vl);
    cudaGetSymbolAddress((void**)&oh, g_oh); cudaGetSymbolAddress((void**)&ol, g_ol);

    // splits
    split32<<<SQ * DIM / 1024, 256>>>(x, xh, xl, SQ * DIM);
    split32<<<DIM * DIM / 1024, 256>>>(wq, wqh, wql, DIM * DIM);
    split32<<<DIM * DIM / 1024, 256>>>(wk, wkh, wkl, DIM * DIM);
    split32<<<DIM * DIM / 1024, 256>>>(wv, wvh, wvl, DIM * DIM);
    split32<<<DIM * DIM / 1024, 256>>>(wo, woh, wol, DIM * DIM);

    cudaFuncSetAttribute(gemm_mma<1>, cudaFuncAttributeMaxDynamicSharedMemorySize, 65536);
    cudaFuncSetAttribute(gemm_mma<0>, cudaFuncAttributeMaxDynamicSharedMemorySize, 65536);
    cudaFuncSetAttribute(attn_mma,    cudaFuncAttributeMaxDynamicSharedMemorySize, ATT_SMEM);

    dim3 ggrid(DIM / 128, SQ / 128);
    gemm_mma<1><<<ggrid, 256, 65536>>>(xh, xl, wqh, wql, bq, nullptr, qh, ql);
    gemm_mma<1><<<ggrid, 256, 65536>>>(xh, xl, wkh, wkl, bk, nullptr, kh, kl);
    gemm_mma<1><<<ggrid, 256, 65536>>>(xh, xl, wvh, wvl, bv, nullptr, vh, vl);

    dim3 agrid(SQ / QT, NH);
    attn_mma<<<agrid, 128, ATT_SMEM>>>(qh, ql, kh, kl, vh, vl, phase, oh, ol);

    gemm_mma<0><<<ggrid, 256, 65536>>>(oh, ol, woh, wol, bo, out, nullptr, nullptr);
}

// round 10
// speedup vs baseline: 1.0715x; 1.0715x over previous
#include <cuda_runtime.h>
#include <cuda_bf16.h>
#include <stdint.h>

#define SQ   4096
#define DIM  1024
#define NH   16
#define HD   64
#define QT   128   // queries per attention block
#define KT   64

// Scratch (allocation-free rule: __device__ globals)
__device__ __nv_bfloat16 g_xh[SQ * DIM],  g_xl[SQ * DIM];
__device__ __nv_bfloat16 g_wqh[DIM * DIM], g_wql[DIM * DIM];
__device__ __nv_bfloat16 g_wkh[DIM * DIM], g_wkl[DIM * DIM];
__device__ __nv_bfloat16 g_wvh[DIM * DIM], g_wvl[DIM * DIM];
__device__ __nv_bfloat16 g_woh[DIM * DIM], g_wol[DIM * DIM];
__device__ __nv_bfloat16 g_qh[SQ * DIM], g_ql[SQ * DIM];
__device__ __nv_bfloat16 g_kh[SQ * DIM], g_kl[SQ * DIM];
__device__ __nv_bfloat16 g_vh[SQ * DIM], g_vl[SQ * DIM];
__device__ __nv_bfloat16 g_oh[SQ * DIM], g_ol[SQ * DIM];

// ---------------------------------------------------------------------------
// Helpers
// ---------------------------------------------------------------------------
__device__ __forceinline__ uint32_t smem_u32(const void* p) {
    uint32_t a;
    asm("{ .reg .u64 t; cvta.to.shared.u64 t, %1; cvt.u32.u64 %0, t; }"
        : "=r"(a) : "l"(p));
    return a;
}
#define SWZ(off)  ((off) ^ (((off) >> 3) & 0x70))   // 128B rows
#define SW64(off) ((off) ^ (((off) >> 3) & 0x30))   // 64B rows

#define CP16(dst, src) \
    asm volatile("cp.async.cg.shared.global [%0], [%1], 16;" :: "r"(dst), "l"(src))
#define CP_COMMIT() asm volatile("cp.async.commit_group;" ::: "memory")
#define CP_WAIT1()  asm volatile("cp.async.wait_group 1;" ::: "memory")

__device__ __forceinline__ void mma_bf16(float* d, const uint32_t* a,
                                         uint32_t b0, uint32_t b1) {
    asm volatile(
        "mma.sync.aligned.m16n8k16.row.col.f32.bf16.bf16.f32 "
        "{%0,%1,%2,%3}, {%4,%5,%6,%7}, {%8,%9}, {%0,%1,%2,%3};"
        : "+f"(d[0]), "+f"(d[1]), "+f"(d[2]), "+f"(d[3])
        : "r"(a[0]), "r"(a[1]), "r"(a[2]), "r"(a[3]), "r"(b0), "r"(b1));
}
__device__ __forceinline__ void ldm_x4(uint32_t* r, uint32_t addr) {
    asm volatile("ldmatrix.sync.aligned.m8n8.x4.shared.b16 {%0,%1,%2,%3}, [%4];"
        : "=r"(r[0]), "=r"(r[1]), "=r"(r[2]), "=r"(r[3]) : "r"(addr));
}
__device__ __forceinline__ void ldm_x4_t(uint32_t* r, uint32_t addr) {
    asm volatile("ldmatrix.sync.aligned.m8n8.x4.trans.shared.b16 {%0,%1,%2,%3}, [%4];"
        : "=r"(r[0]), "=r"(r[1]), "=r"(r[2]), "=r"(r[3]) : "r"(addr));
}

// ---------------------------------------------------------------------------
// fp32 -> bf16 hi/lo split (elementwise)
// ---------------------------------------------------------------------------
__global__ void __launch_bounds__(256) split32(
    const float* __restrict__ in, __nv_bfloat16* __restrict__ hi,
    __nv_bfloat16* __restrict__ lo, int n)
{
    int i = (blockIdx.x * 256 + threadIdx.x) * 4;
    if (i >= n) return;
    float4 f = *(const float4*)(in + i);
    __nv_bfloat162 h0 = __floats2bfloat162_rn(f.x, f.y);
    __nv_bfloat162 h1 = __floats2bfloat162_rn(f.z, f.w);
    __nv_bfloat162 l0 = __floats2bfloat162_rn(f.x - __bfloat162float(h0.x),
                                              f.y - __bfloat162float(h0.y));
    __nv_bfloat162 l1 = __floats2bfloat162_rn(f.z - __bfloat162float(h1.x),
                                              f.w - __bfloat162float(h1.y));
    uint2 hv = {*(uint32_t*)&h0, *(uint32_t*)&h1};
    uint2 lv = {*(uint32_t*)&l0, *(uint32_t*)&l1};
    *(uint2*)(hi + i) = hv;
    *(uint2*)(lo + i) = lv;
}

// ---------------------------------------------------------------------------
// Split-bf16 tensor GEMM: C[M,N] = A @ B^T + bias (unchanged from R7)
// ---------------------------------------------------------------------------
#define GS_STAGE 32768

template<int SPLIT_OUT>
__global__ void __launch_bounds__(256, 1) gemm_mma(
    const __nv_bfloat16* __restrict__ Agh, const __nv_bfloat16* __restrict__ Agl,
    const __nv_bfloat16* __restrict__ Bgh, const __nv_bfloat16* __restrict__ Bgl,
    const float* __restrict__ bias, float* __restrict__ C,
    __nv_bfloat16* __restrict__ Chi, __nv_bfloat16* __restrict__ Clo)
{
    extern __shared__ char sm[];
    const uint32_t smb = smem_u32(sm);
    const int tid = threadIdx.x, lane = tid & 31, warp = tid >> 5;
    const int bm = blockIdx.y * 128, bn = blockIdx.x * 128;
    const int wm = (warp >> 2) * 64, wn = (warp & 3) * 32;

    const int buf = tid >> 6, lrow = tid & 63;
    const __nv_bfloat16* gp[4] = {Agh, Agl, Bgh, Bgl};
    const int rbase = (buf < 2 ? bm : bn) + lrow;
    const __nv_bfloat16* src0 = gp[buf] + (size_t)rbase * DIM;
    const __nv_bfloat16* src1 = gp[buf] + (size_t)(rbase + 64) * DIM;

    float acc[4][4][4];
#pragma unroll
    for (int a = 0; a < 4; a++)
#pragma unroll
        for (int b = 0; b < 4; b++)
#pragma unroll
            for (int c = 0; c < 4; c++) acc[a][b][c] = 0.f;

    {
        uint32_t db = smb + buf * 8192;
#pragma unroll
        for (int i = 0; i < 4; i++) {
            CP16(db + SW64((uint32_t)(lrow * 64 + i * 16)),        src0 + i * 8);
            CP16(db + SW64((uint32_t)((lrow + 64) * 64 + i * 16)), src1 + i * 8);
        }
    }
    CP_COMMIT();

    for (int kt = 0; kt < 32; kt++) {
        if (kt + 1 < 32) {
            uint32_t db = smb + ((kt + 1) & 1) * GS_STAGE + buf * 8192;
            const __nv_bfloat16* s0 = src0 + (kt + 1) * 32;
            const __nv_bfloat16* s1 = src1 + (kt + 1) * 32;
#pragma unroll
            for (int i = 0; i < 4; i++) {
                CP16(db + SW64((uint32_t)(lrow * 64 + i * 16)),        s0 + i * 8);
                CP16(db + SW64((uint32_t)((lrow + 64) * 64 + i * 16)), s1 + i * 8);
            }
        }
        CP_COMMIT();
        CP_WAIT1();
        __syncthreads();

        const uint32_t sb = smb + (kt & 1) * GS_STAGE;
#pragma unroll
        for (int kk = 0; kk < 2; kk++) {
            uint32_t ah[4][4], al[4][4];
#pragma unroll
            for (int mf = 0; mf < 4; mf++) {
                uint32_t off = SW64((uint32_t)((wm + mf * 16 + (lane & 15)) * 64
                                    + kk * 32 + (lane >> 4) * 16));
                ldm_x4(ah[mf], sb + off);
                ldm_x4(al[mf], sb + 8192 + off);
            }
#pragma unroll
            for (int nf = 0; nf < 2; nf++) {
                uint32_t bh[4], bl[4];
                uint32_t off = SW64((uint32_t)((wn + nf * 16 + ((lane >> 4) << 3)
                                    + (lane & 7)) * 64 + kk * 32
                                    + ((lane >> 3) & 1) * 16));
                ldm_x4(bh, sb + 16384 + off);
                ldm_x4(bl, sb + 24576 + off);
#pragma unroll
                for (int mf = 0; mf < 4; mf++) {
                    mma_bf16(acc[mf][2*nf],   ah[mf], bh[0], bh[1]);
                    mma_bf16(acc[mf][2*nf],   ah[mf], bl[0], bl[1]);
                    mma_bf16(acc[mf][2*nf],   al[mf], bh[0], bh[1]);
                    mma_bf16(acc[mf][2*nf+1], ah[mf], bh[2], bh[3]);
                    mma_bf16(acc[mf][2*nf+1], ah[mf], bl[2], bl[3]);
                    mma_bf16(acc[mf][2*nf+1], al[mf], bh[2], bh[3]);
                }
            }
        }
        __syncthreads();
    }

#pragma unroll
    for (int mf = 0; mf < 4; mf++) {
        int r0 = bm + wm + mf * 16 + (lane >> 2);
#pragma unroll
        for (int nf8 = 0; nf8 < 4; nf8++) {
            int c = bn + wn + nf8 * 8 + (lane & 3) * 2;
            float b0 = bias[c], b1 = bias[c + 1];
            float v0 = acc[mf][nf8][0] + b0, v1 = acc[mf][nf8][1] + b1;
            float v2 = acc[mf][nf8][2] + b0, v3 = acc[mf][nf8][3] + b1;
            if (SPLIT_OUT) {
                __nv_bfloat162 h0 = __floats2bfloat162_rn(v0, v1);
                __nv_bfloat162 l0 = __floats2bfloat162_rn(v0 - __bfloat162float(h0.x),
                                                          v1 - __bfloat162float(h0.y));
                __nv_bfloat162 h1 = __floats2bfloat162_rn(v2, v3);
                __nv_bfloat162 l1 = __floats2bfloat162_rn(v2 - __bfloat162float(h1.x),
                                                          v3 - __bfloat162float(h1.y));
                *(uint32_t*)&Chi[(size_t)r0 * DIM + c]       = *(uint32_t*)&h0;
                *(uint32_t*)&Clo[(size_t)r0 * DIM + c]       = *(uint32_t*)&l0;
                *(uint32_t*)&Chi[(size_t)(r0 + 8) * DIM + c] = *(uint32_t*)&h1;
                *(uint32_t*)&Clo[(size_t)(r0 + 8) * DIM + c] = *(uint32_t*)&l1;
            } else {
                float2 w0 = {v0, v1}, w1 = {v2, v3};
                *(float2*)&C[(size_t)r0 * DIM + c]       = w0;
                *(float2*)&C[(size_t)(r0 + 8) * DIM + c] = w1;
            }
        }
    }
}

// ---------------------------------------------------------------------------
// Attention: QT=128, 4 warps x 32 q-rows (2 m-frags) -> half the B-frag LDSM
// traffic of the 8-warp version; 2 CTAs/SM.
// smem: Qh 16KB + Ql 16KB + 2 KV stages x 32KB = 96KB.
// ---------------------------------------------------------------------------
#define SM_QH0  0
#define SM_QL0  16384
#define SM_KV0  32768
#define ATT_SMEM 98304

__global__ void __launch_bounds__(128, 2) attn_mma(
    const __nv_bfloat16* __restrict__ Qh, const __nv_bfloat16* __restrict__ Ql,
    const __nv_bfloat16* __restrict__ Kh, const __nv_bfloat16* __restrict__ Kl,
    const __nv_bfloat16* __restrict__ Vh, const __nv_bfloat16* __restrict__ Vl,
    const float* __restrict__ phase,
    __nv_bfloat16* __restrict__ Oh, __nv_bfloat16* __restrict__ Ol)
{
    extern __shared__ char sm[];
    const uint32_t smb = smem_u32(sm);
    const int tid  = threadIdx.x;
    const int lane = tid & 31;
    const int warp = tid >> 5;           // 0..3
    const int h  = blockIdx.y;
    const int qb = blockIdx.x * QT;
    const int m0 = warp * 32;            // warp owns 32 q-rows (2 m-frags)
    const float ph = phase[h];

    // KV loader role: buf 0:Kh 1:Kl 2:Vh 3:Vl; 32 threads/buf, 2 rows each
    const int buf = tid >> 5, lrow = tid & 31;
    const __nv_bfloat16* gkv[4] = {Kh, Kl, Vh, Vl};
    const __nv_bfloat16* kvsrc0 = gkv[buf] + (size_t)lrow * DIM + h * HD;
    const __nv_bfloat16* kvsrc1 = gkv[buf] + (size_t)(lrow + 32) * DIM + h * HD;

    // prologue: prefetch KV tile 0
    {
        uint32_t db = smb + SM_KV0 + buf * 8192;
#pragma unroll
        for (int i = 0; i < 8; i++) {
            CP16(db + SWZ((uint32_t)(lrow * 128 + i * 16)),        kvsrc0 + i * 8);
            CP16(db + SWZ((uint32_t)((lrow + 32) * 128 + i * 16)), kvsrc1 + i * 8);
        }
    }
    CP_COMMIT();

    // stage Q hi/lo tiles: thread stages row tid for both hi and lo
    {
        const int row = tid;
        const uint4* sh = (const uint4*)(Qh + (size_t)(qb + row) * DIM + h * HD);
        const uint4* sl = (const uint4*)(Ql + (size_t)(qb + row) * DIM + h * HD);
#pragma unroll
        for (int i = 0; i < 8; i++) {
            uint32_t off = SWZ((uint32_t)(row * 128 + i * 16));
            *(uint4*)(sm + SM_QH0 + off) = sh[i];
            *(uint4*)(sm + SM_QL0 + off) = sl[i];
        }
    }
    __syncthreads();

    // persist Qh A-fragments (2 m-frags x 4 k-chunks); Ql reloaded per kk
    uint32_t qfh[2][4][4];
    uint32_t qoff[2][4];
    {
        const uint32_t qcol = (uint32_t)((lane >> 4) * 16);
#pragma unroll
        for (int mf = 0; mf < 2; mf++) {
            const uint32_t qrow = (uint32_t)(m0 + mf * 16 + (lane & 15));
#pragma unroll
            for (int kk = 0; kk < 4; kk++) {
                uint32_t off = SWZ(qrow * 128 + kk * 32 + qcol);
                qoff[mf][kk] = off;
                ldm_x4(qfh[mf][kk], smb + SM_QH0 + off);
            }
        }
    }

    const uint32_t krow = (uint32_t)(((lane >> 4) << 3) + (lane & 7));
    const uint32_t kcol = (uint32_t)(((lane >> 3) & 1) * 16);
    const uint32_t vrow = (uint32_t)((((lane >> 3) & 1) << 3) + (lane & 7));
    const uint32_t vcol = (uint32_t)((lane >> 4) * 16);

    float o[2][8][4];
#pragma unroll
    for (int mf = 0; mf < 2; mf++)
#pragma unroll
        for (int n = 0; n < 8; n++)
#pragma unroll
            for (int e = 0; e < 4; e++) o[mf][n][e] = 0.f;
    float lsum[2][2] = {{0.f, 0.f}, {0.f, 0.f}};

    for (int t = 0; t < SQ / KT; t++) {
        // prefetch next KV tile into other stage
        if (t + 1 < SQ / KT) {
            uint32_t db = smb + SM_KV0 + ((t + 1) & 1) * 32768 + buf * 8192;
            const __nv_bfloat16* s0 = kvsrc0 + (size_t)(t + 1) * KT * DIM;
            const __nv_bfloat16* s1 = kvsrc1 + (size_t)(t + 1) * KT * DIM;
#pragma unroll
            for (int i = 0; i < 8; i++) {
                CP16(db + SWZ((uint32_t)(lrow * 128 + i * 16)),        s0 + i * 8);
                CP16(db + SWZ((uint32_t)((lrow + 32) * 128 + i * 16)), s1 + i * 8);
            }
        }
        CP_COMMIT();
        CP_WAIT1();
        __syncthreads();

        const uint32_t kvb = smb + SM_KV0 + (t & 1) * 32768;

        // ---- S = Q K^T (hh + hl + lh); each B-frag feeds both m-frags ----
        float s[2][8][4];
#pragma unroll
        for (int mf = 0; mf < 2; mf++)
#pragma unroll
            for (int n = 0; n < 8; n++)
#pragma unroll
                for (int e = 0; e < 4; e++) s[mf][n][e] = 0.f;

#pragma unroll
        for (int kk = 0; kk < 4; kk++) {
            uint32_t qfl[2][4];
            ldm_x4(qfl[0], smb + SM_QL0 + qoff[0][kk]);
            ldm_x4(qfl[1], smb + SM_QL0 + qoff[1][kk]);
#pragma unroll
            for (int np = 0; np < 4; np++) {
                uint32_t bh[4], bl[4];
                uint32_t off = SWZ((np * 16 + krow) * 128 + kk * 32 + kcol);
                ldm_x4(bh, kvb + off);
                ldm_x4(bl, kvb + 8192 + off);
#pragma unroll
                for (int mf = 0; mf < 2; mf++) {
                    mma_bf16(s[mf][2*np],   qfh[mf][kk], bh[0], bh[1]);
                    mma_bf16(s[mf][2*np],   qfh[mf][kk], bl[0], bl[1]);
                    mma_bf16(s[mf][2*np],   qfl[mf],     bh[0], bh[1]);
                    mma_bf16(s[mf][2*np+1], qfh[mf][kk], bh[2], bh[3]);
                    mma_bf16(s[mf][2*np+1], qfh[mf][kk], bl[2], bl[3]);
                    mma_bf16(s[mf][2*np+1], qfl[mf],     bh[2], bh[3]);
                }
            }
        }

        // ---- modulation + exp(. - 16) ----
#pragma unroll
        for (int mf = 0; mf < 2; mf++)
#pragma unroll
            for (int n = 0; n < 8; n++) {
#pragma unroll
                for (int e = 0; e < 4; e++) {
                    float sc = s[mf][n][e] * 0.125f;
                    float m  = sc * (1.f + 0.1f * __cosf(ph * sc));
                    s[mf][n][e] = __expf(m - 16.f);
                }
                lsum[mf][0] += s[mf][n][0] + s[mf][n][1];
                lsum[mf][1] += s[mf][n][2] + s[mf][n][3];
            }

        // ---- O += P V; each V-frag feeds both m-frags ----
#pragma unroll
        for (int kk = 0; kk < 4; kk++) {
            const int t0 = 2 * kk, t1 = 2 * kk + 1;
            uint32_t ah[2][4], al[2][4];
#pragma unroll
            for (int mf = 0; mf < 2; mf++) {
                const float* pv[4] = {&s[mf][t0][0], &s[mf][t0][2],
                                      &s[mf][t1][0], &s[mf][t1][2]};
#pragma unroll
                for (int q = 0; q < 4; q++) {
                    float p0 = pv[q][0], p1 = pv[q][1];
                    __nv_bfloat162 hp = __floats2bfloat162_rn(p0, p1);
                    float r0 = p0 - __bfloat162float(hp.x);
                    float r1 = p1 - __bfloat162float(hp.y);
                    __nv_bfloat162 lp = __floats2bfloat162_rn(r0, r1);
                    ah[mf][q] = *(uint32_t*)&hp;
                    al[mf][q] = *(uint32_t*)&lp;
                }
            }
#pragma unroll
            for (int dp = 0; dp < 4; dp++) {
                uint32_t bh[4], bl[4];
                uint32_t off = SWZ((kk * 16 + vrow) * 128 + dp * 32 + vcol);
                ldm_x4_t(bh, kvb + 16384 + off);
                ldm_x4_t(bl, kvb + 24576 + off);
#pragma unroll
                for (int mf = 0; mf < 2; mf++) {
                    mma_bf16(o[mf][2*dp],   ah[mf], bh[0], bh[1]);
                    mma_bf16(o[mf][2*dp],   ah[mf], bl[0], bl[1]);
                    mma_bf16(o[mf][2*dp],   al[mf], bh[0], bh[1]);
                    mma_bf16(o[mf][2*dp+1], ah[mf], bh[2], bh[3]);
                    mma_bf16(o[mf][2*dp+1], ah[mf], bl[2], bl[3]);
                    mma_bf16(o[mf][2*dp+1], al[mf], bh[2], bh[3]);
                }
            }
        }
        __syncthreads();
    }

    // ---- finalize: l-reduce, scale, write split bf16 ----
#pragma unroll
    for (int mf = 0; mf < 2; mf++) {
        float l0 = lsum[mf][0], l8 = lsum[mf][1];
        l0 += __shfl_xor_sync(0xffffffffu, l0, 1);
        l0 += __shfl_xor_sync(0xffffffffu, l0, 2);
        l8 += __shfl_xor_sync(0xffffffffu, l8, 1);
        l8 += __shfl_xor_sync(0xffffffffu, l8, 2);
        const float inv0 = 1.f / l0;
        const float inv8 = 1.f / l8;

        const int row0 = qb + m0 + mf * 16 + (lane >> 2);
        const int colb = h * HD + (lane & 3) * 2;
#pragma unroll
        for (int n = 0; n < 8; n++) {
            float a0 = o[mf][n][0] * inv0, a1 = o[mf][n][1] * inv0;
            float b0 = o[mf][n][2] * inv8, b1 = o[mf][n][3] * inv8;
            __nv_bfloat162 h0 = __floats2bfloat162_rn(a0, a1);
            __nv_bfloat162 l0p = __floats2bfloat162_rn(a0 - __bfloat162float(h0.x),
                                                       a1 - __bfloat162float(h0.y));
            __nv_bfloat162 h1 = __floats2bfloat162_rn(b0, b1);
            __nv_bfloat162 l1p = __floats2bfloat162_rn(b0 - __bfloat162float(h1.x),
                                                       b1 - __bfloat162float(h1.y));
            size_t i0 = (size_t)row0 * DIM + colb + n * 8;
            size_t i1 = (size_t)(row0 + 8) * DIM + colb + n * 8;
            *(uint32_t*)&Oh[i0] = *(uint32_t*)&h0;
            *(uint32_t*)&Ol[i0] = *(uint32_t*)&l0p;
            *(uint32_t*)&Oh[i1] = *(uint32_t*)&h1;
            *(uint32_t*)&Ol[i1] = *(uint32_t*)&l1p;
        }
    }
}

// ---------------------------------------------------------------------------
extern "C" void kernel_launch(void* const* d_in, const int* in_sizes, int n_in,
                              void* d_out, int out_size)
{
    const float* x     = (const float*)d_in[0];
    const float* wq    = (const float*)d_in[1];
    const float* bq    = (const float*)d_in[2];
    const float* wk    = (const float*)d_in[3];
    const float* bk    = (const float*)d_in[4];
    const float* wv    = (const float*)d_in[5];
    const float* bv    = (const float*)d_in[6];
    const float* wo    = (const float*)d_in[7];
    const float* bo    = (const float*)d_in[8];
    const float* phase = (const float*)d_in[9];
    float* out = (float*)d_out;

    __nv_bfloat16 *xh, *xl, *wqh, *wql, *wkh, *wkl, *wvh, *wvl, *woh, *wol;
    __nv_bfloat16 *qh, *ql, *kh, *kl, *vh, *vl, *oh, *ol;
    cudaGetSymbolAddress((void**)&xh,  g_xh);  cudaGetSymbolAddress((void**)&xl,  g_xl);
    cudaGetSymbolAddress((void**)&wqh, g_wqh); cudaGetSymbolAddress((void**)&wql, g_wql);
    cudaGetSymbolAddress((void**)&wkh, g_wkh); cudaGetSymbolAddress((void**)&wkl, g_wkl);
    cudaGetSymbolAddress((void**)&wvh, g_wvh); cudaGetSymbolAddress((void**)&wvl, g_wvl);
    cudaGetSymbolAddress((void**)&woh, g_woh); cudaGetSymbolAddress((void**)&wol, g_wol);
    cudaGetSymbolAddress((void**)&qh, g_qh); cudaGetSymbolAddress((void**)&ql, g_ql);
    cudaGetSymbolAddress((void**)&kh, g_kh); cudaGetSymbolAddress((void**)&kl, g_kl);
    cudaGetSymbolAddress((void**)&vh, g_vh); cudaGetSymbolAddress((void**)&vl, g_vl);
    cudaGetSymbolAddress((void**)&oh, g_oh); cudaGetSymbolAddress((void**)&ol, g_ol);

    // splits
    split32<<<SQ * DIM / 1024, 256>>>(x, xh, xl, SQ * DIM);
    split32<<<DIM * DIM / 1024, 256>>>(wq, wqh, wql, DIM * DIM);
    split32<<<DIM * DIM / 1024, 256>>>(wk, wkh, wkl, DIM * DIM);
    split32<<<DIM * DIM / 1024, 256>>>(wv, wvh, wvl, DIM * DIM);
    split32<<<DIM * DIM / 1024, 256>>>(wo, woh, wol, DIM * DIM);

    cudaFuncSetAttribute(gemm_mma<1>, cudaFuncAttributeMaxDynamicSharedMemorySize, 65536);
    cudaFuncSetAttribute(gemm_mma<0>, cudaFuncAttributeMaxDynamicSharedMemorySize, 65536);
    cudaFuncSetAttribute(attn_mma,    cudaFuncAttributeMaxDynamicSharedMemorySize, ATT_SMEM);

    dim3 ggrid(DIM / 128, SQ / 128);
    gemm_mma<1><<<ggrid, 256, 65536>>>(xh, xl, wqh, wql, bq, nullptr, qh, ql);
    gemm_mma<1><<<ggrid, 256, 65536>>>(xh, xl, wkh, wkl, bk, nullptr, kh, kl);
    gemm_mma<1><<<ggrid, 256, 65536>>>(xh, xl, wvh, wvl, bv, nullptr, vh, vl);

    dim3 agrid(SQ / QT, NH);
    attn_mma<<<agrid, 128, ATT_SMEM>>>(qh, ql, kh, kl, vh, vl, phase, oh, ol);

    gemm_mma<0><<<ggrid, 256, 65536>>>(oh, ol, woh, wol, bo, out, nullptr, nullptr);
}

// round 11
// speedup vs baseline: 1.2400x; 1.1572x over previous
#include <cuda_runtime.h>
#include <cuda_bf16.h>
#include <cuda_fp16.h>
#include <stdint.h>

#define SQ   4096
#define DIM  1024
#define NH   16
#define HD   64
#define QT   128   // queries per attention block
#define KT   64

// Scratch (allocation-free rule: __device__ globals)
__device__ __nv_bfloat16 g_xh[SQ * DIM],  g_xl[SQ * DIM];
__device__ __nv_bfloat16 g_wqh[DIM * DIM], g_wql[DIM * DIM];
__device__ __nv_bfloat16 g_wkh[DIM * DIM], g_wkl[DIM * DIM];
__device__ __nv_bfloat16 g_wvh[DIM * DIM], g_wvl[DIM * DIM];
__device__ __nv_bfloat16 g_woh[DIM * DIM], g_wol[DIM * DIM];
__device__ __nv_bfloat16 g_qh[SQ * DIM], g_ql[SQ * DIM];
__device__ __nv_bfloat16 g_kh[SQ * DIM], g_kl[SQ * DIM];
__device__ __half        g_vf[SQ * DIM];
__device__ __nv_bfloat16 g_oh[SQ * DIM], g_ol[SQ * DIM];

// ---------------------------------------------------------------------------
// Helpers
// ---------------------------------------------------------------------------
__device__ __forceinline__ uint32_t smem_u32(const void* p) {
    uint32_t a;
    asm("{ .reg .u64 t; cvta.to.shared.u64 t, %1; cvt.u32.u64 %0, t; }"
        : "=r"(a) : "l"(p));
    return a;
}
#define SWZ(off)  ((off) ^ (((off) >> 3) & 0x70))   // 128B rows
#define SW64(off) ((off) ^ (((off) >> 3) & 0x30))   // 64B rows

#define CP16(dst, src) \
    asm volatile("cp.async.cg.shared.global [%0], [%1], 16;" :: "r"(dst), "l"(src))
#define CP_COMMIT() asm volatile("cp.async.commit_group;" ::: "memory")
#define CP_WAIT1()  asm volatile("cp.async.wait_group 1;" ::: "memory")

__device__ __forceinline__ void mma_bf16(float* d, const uint32_t* a,
                                         uint32_t b0, uint32_t b1) {
    asm volatile(
        "mma.sync.aligned.m16n8k16.row.col.f32.bf16.bf16.f32 "
        "{%0,%1,%2,%3}, {%4,%5,%6,%7}, {%8,%9}, {%0,%1,%2,%3};"
        : "+f"(d[0]), "+f"(d[1]), "+f"(d[2]), "+f"(d[3])
        : "r"(a[0]), "r"(a[1]), "r"(a[2]), "r"(a[3]), "r"(b0), "r"(b1));
}
__device__ __forceinline__ void mma_fp16(float* d, const uint32_t* a,
                                         uint32_t b0, uint32_t b1) {
    asm volatile(
        "mma.sync.aligned.m16n8k16.row.col.f32.f16.f16.f32 "
        "{%0,%1,%2,%3}, {%4,%5,%6,%7}, {%8,%9}, {%0,%1,%2,%3};"
        : "+f"(d[0]), "+f"(d[1]), "+f"(d[2]), "+f"(d[3])
        : "r"(a[0]), "r"(a[1]), "r"(a[2]), "r"(a[3]), "r"(b0), "r"(b1));
}
__device__ __forceinline__ void ldm_x4(uint32_t* r, uint32_t addr) {
    asm volatile("ldmatrix.sync.aligned.m8n8.x4.shared.b16 {%0,%1,%2,%3}, [%4];"
        : "=r"(r[0]), "=r"(r[1]), "=r"(r[2]), "=r"(r[3]) : "r"(addr));
}
__device__ __forceinline__ void ldm_x4_t(uint32_t* r, uint32_t addr) {
    asm volatile("ldmatrix.sync.aligned.m8n8.x4.trans.shared.b16 {%0,%1,%2,%3}, [%4];"
        : "=r"(r[0]), "=r"(r[1]), "=r"(r[2]), "=r"(r[3]) : "r"(addr));
}

// ---------------------------------------------------------------------------
// fp32 -> bf16 hi/lo split (elementwise)
// ---------------------------------------------------------------------------
__global__ void __launch_bounds__(256) split32(
    const float* __restrict__ in, __nv_bfloat16* __restrict__ hi,
    __nv_bfloat16* __restrict__ lo, int n)
{
    int i = (blockIdx.x * 256 + threadIdx.x) * 4;
    if (i >= n) return;
    float4 f = *(const float4*)(in + i);
    __nv_bfloat162 h0 = __floats2bfloat162_rn(f.x, f.y);
    __nv_bfloat162 h1 = __floats2bfloat162_rn(f.z, f.w);
    __nv_bfloat162 l0 = __floats2bfloat162_rn(f.x - __bfloat162float(h0.x),
                                              f.y - __bfloat162float(h0.y));
    __nv_bfloat162 l1 = __floats2bfloat162_rn(f.z - __bfloat162float(h1.x),
                                              f.w - __bfloat162float(h1.y));
    uint2 hv = {*(uint32_t*)&h0, *(uint32_t*)&h1};
    uint2 lv = {*(uint32_t*)&l0, *(uint32_t*)&l1};
    *(uint2*)(hi + i) = hv;
    *(uint2*)(lo + i) = lv;
}

// ---------------------------------------------------------------------------
// Split-bf16 tensor GEMM: C[M,N] = A @ B^T + bias.
// OUT_MODE: 0 -> fp32 C; 1 -> bf16 hi/lo pair; 2 -> fp16 single.
// ---------------------------------------------------------------------------
#define GS_STAGE 32768

template<int OUT_MODE>
__global__ void __launch_bounds__(256, 1) gemm_mma(
    const __nv_bfloat16* __restrict__ Agh, const __nv_bfloat16* __restrict__ Agl,
    const __nv_bfloat16* __restrict__ Bgh, const __nv_bfloat16* __restrict__ Bgl,
    const float* __restrict__ bias, float* __restrict__ C,
    __nv_bfloat16* __restrict__ Chi, __nv_bfloat16* __restrict__ Clo,
    __half* __restrict__ Cf16)
{
    extern __shared__ char sm[];
    const uint32_t smb = smem_u32(sm);
    const int tid = threadIdx.x, lane = tid & 31, warp = tid >> 5;
    const int bm = blockIdx.y * 128, bn = blockIdx.x * 128;
    const int wm = (warp >> 2) * 64, wn = (warp & 3) * 32;

    const int buf = tid >> 6, lrow = tid & 63;
    const __nv_bfloat16* gp[4] = {Agh, Agl, Bgh, Bgl};
    const int rbase = (buf < 2 ? bm : bn) + lrow;
    const __nv_bfloat16* src0 = gp[buf] + (size_t)rbase * DIM;
    const __nv_bfloat16* src1 = gp[buf] + (size_t)(rbase + 64) * DIM;

    float acc[4][4][4];
#pragma unroll
    for (int a = 0; a < 4; a++)
#pragma unroll
        for (int b = 0; b < 4; b++)
#pragma unroll
            for (int c = 0; c < 4; c++) acc[a][b][c] = 0.f;

    {
        uint32_t db = smb + buf * 8192;
#pragma unroll
        for (int i = 0; i < 4; i++) {
            CP16(db + SW64((uint32_t)(lrow * 64 + i * 16)),        src0 + i * 8);
            CP16(db + SW64((uint32_t)((lrow + 64) * 64 + i * 16)), src1 + i * 8);
        }
    }
    CP_COMMIT();

    for (int kt = 0; kt < 32; kt++) {
        if (kt + 1 < 32) {
            uint32_t db = smb + ((kt + 1) & 1) * GS_STAGE + buf * 8192;
            const __nv_bfloat16* s0 = src0 + (kt + 1) * 32;
            const __nv_bfloat16* s1 = src1 + (kt + 1) * 32;
#pragma unroll
            for (int i = 0; i < 4; i++) {
                CP16(db + SW64((uint32_t)(lrow * 64 + i * 16)),        s0 + i * 8);
                CP16(db + SW64((uint32_t)((lrow + 64) * 64 + i * 16)), s1 + i * 8);
            }
        }
        CP_COMMIT();
        CP_WAIT1();
        __syncthreads();

        const uint32_t sb = smb + (kt & 1) * GS_STAGE;
#pragma unroll
        for (int kk = 0; kk < 2; kk++) {
            uint32_t ah[4][4], al[4][4];
#pragma unroll
            for (int mf = 0; mf < 4; mf++) {
                uint32_t off = SW64((uint32_t)((wm + mf * 16 + (lane & 15)) * 64
                                    + kk * 32 + (lane >> 4) * 16));
                ldm_x4(ah[mf], sb + off);
                ldm_x4(al[mf], sb + 8192 + off);
            }
#pragma unroll
            for (int nf = 0; nf < 2; nf++) {
                uint32_t bh[4], bl[4];
                uint32_t off = SW64((uint32_t)((wn + nf * 16 + ((lane >> 4) << 3)
                                    + (lane & 7)) * 64 + kk * 32
                                    + ((lane >> 3) & 1) * 16));
                ldm_x4(bh, sb + 16384 + off);
                ldm_x4(bl, sb + 24576 + off);
#pragma unroll
                for (int mf = 0; mf < 4; mf++) {
                    mma_bf16(acc[mf][2*nf],   ah[mf], bh[0], bh[1]);
                    mma_bf16(acc[mf][2*nf],   ah[mf], bl[0], bl[1]);
                    mma_bf16(acc[mf][2*nf],   al[mf], bh[0], bh[1]);
                    mma_bf16(acc[mf][2*nf+1], ah[mf], bh[2], bh[3]);
                    mma_bf16(acc[mf][2*nf+1], ah[mf], bl[2], bl[3]);
                    mma_bf16(acc[mf][2*nf+1], al[mf], bh[2], bh[3]);
                }
            }
        }
        __syncthreads();
    }

#pragma unroll
    for (int mf = 0; mf < 4; mf++) {
        int r0 = bm + wm + mf * 16 + (lane >> 2);
#pragma unroll
        for (int nf8 = 0; nf8 < 4; nf8++) {
            int c = bn + wn + nf8 * 8 + (lane & 3) * 2;
            float b0 = bias[c], b1 = bias[c + 1];
            float v0 = acc[mf][nf8][0] + b0, v1 = acc[mf][nf8][1] + b1;
            float v2 = acc[mf][nf8][2] + b0, v3 = acc[mf][nf8][3] + b1;
            if (OUT_MODE == 1) {
                __nv_bfloat162 h0 = __floats2bfloat162_rn(v0, v1);
                __nv_bfloat162 l0 = __floats2bfloat162_rn(v0 - __bfloat162float(h0.x),
                                                          v1 - __bfloat162float(h0.y));
                __nv_bfloat162 h1 = __floats2bfloat162_rn(v2, v3);
                __nv_bfloat162 l1 = __floats2bfloat162_rn(v2 - __bfloat162float(h1.x),
                                                          v3 - __bfloat162float(h1.y));
                *(uint32_t*)&Chi[(size_t)r0 * DIM + c]       = *(uint32_t*)&h0;
                *(uint32_t*)&Clo[(size_t)r0 * DIM + c]       = *(uint32_t*)&l0;
                *(uint32_t*)&Chi[(size_t)(r0 + 8) * DIM + c] = *(uint32_t*)&h1;
                *(uint32_t*)&Clo[(size_t)(r0 + 8) * DIM + c] = *(uint32_t*)&l1;
            } else if (OUT_MODE == 2) {
                __half2 f0 = __floats2half2_rn(v0, v1);
                __half2 f1 = __floats2half2_rn(v2, v3);
                *(uint32_t*)&Cf16[(size_t)r0 * DIM + c]       = *(uint32_t*)&f0;
                *(uint32_t*)&Cf16[(size_t)(r0 + 8) * DIM + c] = *(uint32_t*)&f1;
            } else {
                float2 w0 = {v0, v1}, w1 = {v2, v3};
                *(float2*)&C[(size_t)r0 * DIM + c]       = w0;
                *(float2*)&C[(size_t)(r0 + 8) * DIM + c] = w1;
            }
        }
    }
}

// ---------------------------------------------------------------------------
// Attention: QK split-bf16 (3 MMAs), PV fp16 single (1 MMA).
// QT=128, 4 warps x 32 q-rows; 2 CTAs/SM.
// smem: Qh 16KB + Ql 16KB + 2 KV stages x 24KB (Kh 8K, Kl 8K, Vf16 8K) = 80KB.
// Softmax: fixed shift exp(m - 4): P in fp16 normal range; shift cancels in /L.
// ---------------------------------------------------------------------------
#define SM_QH0  0
#define SM_QL0  16384
#define SM_KV0  32768
#define KV_STAGE 24576
#define ATT_SMEM (32768 + 2 * KV_STAGE)   // 81920

__global__ void __launch_bounds__(128, 2) attn_mma(
    const __nv_bfloat16* __restrict__ Qh, const __nv_bfloat16* __restrict__ Ql,
    const __nv_bfloat16* __restrict__ Kh, const __nv_bfloat16* __restrict__ Kl,
    const __half* __restrict__ Vf,
    const float* __restrict__ phase,
    __nv_bfloat16* __restrict__ Oh, __nv_bfloat16* __restrict__ Ol)
{
    extern __shared__ char sm[];
    const uint32_t smb = smem_u32(sm);
    const int tid  = threadIdx.x;
    const int lane = tid & 31;
    const int warp = tid >> 5;           // 0..3
    const int h  = blockIdx.y;
    const int qb = blockIdx.x * QT;
    const int m0 = warp * 32;            // warp owns 32 q-rows (2 m-frags)
    const float ph = phase[h];

    // KV loader: grp 0: Kh (2 rows), grp 1: Kl (2 rows), grp 2/3: V (1 row each half)
    const int grp = tid >> 5, lrow = tid & 31;
    const __nv_bfloat16* kbase = (grp == 1 ? Kl : Kh);
    const int vrow_ld = lrow + (grp - 2) * 32;

    // prologue: prefetch KV tile 0
    {
        uint32_t db = smb + SM_KV0;
        if (grp < 2) {
            const __nv_bfloat16* s0 = kbase + (size_t)lrow * DIM + h * HD;
            const __nv_bfloat16* s1 = s0 + (size_t)32 * DIM;
#pragma unroll
            for (int i = 0; i < 8; i++) {
                CP16(db + grp * 8192 + SWZ((uint32_t)(lrow * 128 + i * 16)),        s0 + i * 8);
                CP16(db + grp * 8192 + SWZ((uint32_t)((lrow + 32) * 128 + i * 16)), s1 + i * 8);
            }
        } else {
            const __half* sv = Vf + (size_t)vrow_ld * DIM + h * HD;
#pragma unroll
            for (int i = 0; i < 8; i++)
                CP16(db + 16384 + SWZ((uint32_t)(vrow_ld * 128 + i * 16)), sv + i * 8);
        }
    }
    CP_COMMIT();

    // stage Q hi/lo tiles: thread stages row tid for both hi and lo
    {
        const int row = tid;
        const uint4* sh = (const uint4*)(Qh + (size_t)(qb + row) * DIM + h * HD);
        const uint4* sl = (const uint4*)(Ql + (size_t)(qb + row) * DIM + h * HD);
#pragma unroll
        for (int i = 0; i < 8; i++) {
            uint32_t off = SWZ((uint32_t)(row * 128 + i * 16));
            *(uint4*)(sm + SM_QH0 + off) = sh[i];
            *(uint4*)(sm + SM_QL0 + off) = sl[i];
        }
    }
    __syncthreads();

    // persist Qh A-fragments (2 m-frags x 4 k-chunks); Ql reloaded per kk
    uint32_t qfh[2][4][4];
    uint32_t qoff[2][4];
    {
        const uint32_t qcol = (uint32_t)((lane >> 4) * 16);
#pragma unroll
        for (int mf = 0; mf < 2; mf++) {
            const uint32_t qrow = (uint32_t)(m0 + mf * 16 + (lane & 15));
#pragma unroll
            for (int kk = 0; kk < 4; kk++) {
                uint32_t off = SWZ(qrow * 128 + kk * 32 + qcol);
                qoff[mf][kk] = off;
                ldm_x4(qfh[mf][kk], smb + SM_QH0 + off);
            }
        }
    }

    const uint32_t krow = (uint32_t)(((lane >> 4) << 3) + (lane & 7));
    const uint32_t kcol = (uint32_t)(((lane >> 3) & 1) * 16);
    const uint32_t vrow = (uint32_t)((((lane >> 3) & 1) << 3) + (lane & 7));
    const uint32_t vcol = (uint32_t)((lane >> 4) * 16);

    float o[2][8][4];
#pragma unroll
    for (int mf = 0; mf < 2; mf++)
#pragma unroll
        for (int n = 0; n < 8; n++)
#pragma unroll
            for (int e = 0; e < 4; e++) o[mf][n][e] = 0.f;
    float lsum[2][2] = {{0.f, 0.f}, {0.f, 0.f}};

    for (int t = 0; t < SQ / KT; t++) {
        // prefetch next KV tile into other stage
        if (t + 1 < SQ / KT) {
            uint32_t db = smb + SM_KV0 + ((t + 1) & 1) * KV_STAGE;
            const size_t roff = (size_t)(t + 1) * KT * DIM;
            if (grp < 2) {
                const __nv_bfloat16* s0 = kbase + roff + (size_t)lrow * DIM + h * HD;
                const __nv_bfloat16* s1 = s0 + (size_t)32 * DIM;
#pragma unroll
                for (int i = 0; i < 8; i++) {
                    CP16(db + grp * 8192 + SWZ((uint32_t)(lrow * 128 + i * 16)),        s0 + i * 8);
                    CP16(db + grp * 8192 + SWZ((uint32_t)((lrow + 32) * 128 + i * 16)), s1 + i * 8);
                }
            } else {
                const __half* sv = Vf + roff + (size_t)vrow_ld * DIM + h * HD;
#pragma unroll
                for (int i = 0; i < 8; i++)
                    CP16(db + 16384 + SWZ((uint32_t)(vrow_ld * 128 + i * 16)), sv + i * 8);
            }
        }
        CP_COMMIT();
        CP_WAIT1();
        __syncthreads();

        const uint32_t kvb = smb + SM_KV0 + (t & 1) * KV_STAGE;

        // ---- S = Q K^T (hh + hl + lh); each B-frag feeds both m-frags ----
        float s[2][8][4];
#pragma unroll
        for (int mf = 0; mf < 2; mf++)
#pragma unroll
            for (int n = 0; n < 8; n++)
#pragma unroll
                for (int e = 0; e < 4; e++) s[mf][n][e] = 0.f;

#pragma unroll
        for (int kk = 0; kk < 4; kk++) {
            uint32_t qfl[2][4];
            ldm_x4(qfl[0], smb + SM_QL0 + qoff[0][kk]);
            ldm_x4(qfl[1], smb + SM_QL0 + qoff[1][kk]);
#pragma unroll
            for (int np = 0; np < 4; np++) {
                uint32_t bh[4], bl[4];
                uint32_t off = SWZ((np * 16 + krow) * 128 + kk * 32 + kcol);
                ldm_x4(bh, kvb + off);
                ldm_x4(bl, kvb + 8192 + off);
#pragma unroll
                for (int mf = 0; mf < 2; mf++) {
                    mma_bf16(s[mf][2*np],   qfh[mf][kk], bh[0], bh[1]);
                    mma_bf16(s[mf][2*np],   qfh[mf][kk], bl[0], bl[1]);
                    mma_bf16(s[mf][2*np],   qfl[mf],     bh[0], bh[1]);
                    mma_bf16(s[mf][2*np+1], qfh[mf][kk], bh[2], bh[3]);
                    mma_bf16(s[mf][2*np+1], qfh[mf][kk], bl[2], bl[3]);
                    mma_bf16(s[mf][2*np+1], qfl[mf],     bh[2], bh[3]);
                }
            }
        }

        // ---- modulation + exp(. - 4) ----
#pragma unroll
        for (int mf = 0; mf < 2; mf++)
#pragma unroll
            for (int n = 0; n < 8; n++) {
#pragma unroll
                for (int e = 0; e < 4; e++) {
                    float sc = s[mf][n][e] * 0.125f;
                    float m  = sc * (1.f + 0.1f * __cosf(ph * sc));
                    s[mf][n][e] = __expf(m - 4.f);
                }
                lsum[mf][0] += s[mf][n][0] + s[mf][n][1];
                lsum[mf][1] += s[mf][n][2] + s[mf][n][3];
            }

        // ---- O += P V (fp16 single product) ----
#pragma unroll
        for (int kk = 0; kk < 4; kk++) {
            const int t0 = 2 * kk, t1 = 2 * kk + 1;
            uint32_t ah[2][4];
#pragma unroll
            for (int mf = 0; mf < 2; mf++) {
                __half2 p0 = __floats2half2_rn(s[mf][t0][0], s[mf][t0][1]);
                __half2 p1 = __floats2half2_rn(s[mf][t0][2], s[mf][t0][3]);
                __half2 p2 = __floats2half2_rn(s[mf][t1][0], s[mf][t1][1]);
                __half2 p3 = __floats2half2_rn(s[mf][t1][2], s[mf][t1][3]);
                ah[mf][0] = *(uint32_t*)&p0;
                ah[mf][1] = *(uint32_t*)&p1;
                ah[mf][2] = *(uint32_t*)&p2;
                ah[mf][3] = *(uint32_t*)&p3;
            }
#pragma unroll
            for (int dp = 0; dp < 4; dp++) {
                uint32_t bv[4];
                uint32_t off = SWZ((kk * 16 + vrow) * 128 + dp * 32 + vcol);
                ldm_x4_t(bv, kvb + 16384 + off);
#pragma unroll
                for (int mf = 0; mf < 2; mf++) {
                    mma_fp16(o[mf][2*dp],   ah[mf], bv[0], bv[1]);
                    mma_fp16(o[mf][2*dp+1], ah[mf], bv[2], bv[3]);
                }
            }
        }
        __syncthreads();
    }

    // ---- finalize: l-reduce, scale, write split bf16 ----
#pragma unroll
    for (int mf = 0; mf < 2; mf++) {
        float l0 = lsum[mf][0], l8 = lsum[mf][1];
        l0 += __shfl_xor_sync(0xffffffffu, l0, 1);
        l0 += __shfl_xor_sync(0xffffffffu, l0, 2);
        l8 += __shfl_xor_sync(0xffffffffu, l8, 1);
        l8 += __shfl_xor_sync(0xffffffffu, l8, 2);
        const float inv0 = 1.f / l0;
        const float inv8 = 1.f / l8;

        const int row0 = qb + m0 + mf * 16 + (lane >> 2);
        const int colb = h * HD + (lane & 3) * 2;
#pragma unroll
        for (int n = 0; n < 8; n++) {
            float a0 = o[mf][n][0] * inv0, a1 = o[mf][n][1] * inv0;
            float b0 = o[mf][n][2] * inv8, b1 = o[mf][n][3] * inv8;
            __nv_bfloat162 h0 = __floats2bfloat162_rn(a0, a1);
            __nv_bfloat162 l0p = __floats2bfloat162_rn(a0 - __bfloat162float(h0.x),
                                                       a1 - __bfloat162float(h0.y));
            __nv_bfloat162 h1 = __floats2bfloat162_rn(b0, b1);
            __nv_bfloat162 l1p = __floats2bfloat162_rn(b0 - __bfloat162float(h1.x),
                                                       b1 - __bfloat162float(h1.y));
            size_t i0 = (size_t)row0 * DIM + colb + n * 8;
            size_t i1 = (size_t)(row0 + 8) * DIM + colb + n * 8;
            *(uint32_t*)&Oh[i0] = *(uint32_t*)&h0;
            *(uint32_t*)&Ol[i0] = *(uint32_t*)&l0p;
            *(uint32_t*)&Oh[i1] = *(uint32_t*)&h1;
            *(uint32_t*)&Ol[i1] = *(uint32_t*)&l1p;
        }
    }
}

// ---------------------------------------------------------------------------
extern "C" void kernel_launch(void* const* d_in, const int* in_sizes, int n_in,
                              void* d_out, int out_size)
{
    const float* x     = (const float*)d_in[0];
    const float* wq    = (const float*)d_in[1];
    const float* bq    = (const float*)d_in[2];
    const float* wk    = (const float*)d_in[3];
    const float* bk    = (const float*)d_in[4];
    const float* wv    = (const float*)d_in[5];
    const float* bv    = (const float*)d_in[6];
    const float* wo    = (const float*)d_in[7];
    const float* bo    = (const float*)d_in[8];
    const float* phase = (const float*)d_in[9];
    float* out = (float*)d_out;

    __nv_bfloat16 *xh, *xl, *wqh, *wql, *wkh, *wkl, *wvh, *wvl, *woh, *wol;
    __nv_bfloat16 *qh, *ql, *kh, *kl, *oh, *ol;
    __half *vf;
    cudaGetSymbolAddress((void**)&xh,  g_xh);  cudaGetSymbolAddress((void**)&xl,  g_xl);
    cudaGetSymbolAddress((void**)&wqh, g_wqh); cudaGetSymbolAddress((void**)&wql, g_wql);
    cudaGetSymbolAddress((void**)&wkh, g_wkh); cudaGetSymbolAddress((void**)&wkl, g_wkl);
    cudaGetSymbolAddress((void**)&wvh, g_wvh); cudaGetSymbolAddress((void**)&wvl, g_wvl);
    cudaGetSymbolAddress((void**)&woh, g_woh); cudaGetSymbolAddress((void**)&wol, g_wol);
    cudaGetSymbolAddress((void**)&qh, g_qh); cudaGetSymbolAddress((void**)&ql, g_ql);
    cudaGetSymbolAddress((void**)&kh, g_kh); cudaGetSymbolAddress((void**)&kl, g_kl);
    cudaGetSymbolAddress((void**)&vf, g_vf);
    cudaGetSymbolAddress((void**)&oh, g_oh); cudaGetSymbolAddress((void**)&ol, g_ol);

    // splits
    split32<<<SQ * DIM / 1024, 256>>>(x, xh, xl, SQ * DIM);
    split32<<<DIM * DIM / 1024, 256>>>(wq, wqh, wql, DIM * DIM);
    split32<<<DIM * DIM / 1024, 256>>>(wk, wkh, wkl, DIM * DIM);
    split32<<<DIM * DIM / 1024, 256>>>(wv, wvh, wvl, DIM * DIM);
    split32<<<DIM * DIM / 1024, 256>>>(wo, woh, wol, DIM * DIM);

    cudaFuncSetAttribute(gemm_mma<0>, cudaFuncAttributeMaxDynamicSharedMemorySize, 65536);
    cudaFuncSetAttribute(gemm_mma<1>, cudaFuncAttributeMaxDynamicSharedMemorySize, 65536);
    cudaFuncSetAttribute(gemm_mma<2>, cudaFuncAttributeMaxDynamicSharedMemorySize, 65536);
    cudaFuncSetAttribute(attn_mma,    cudaFuncAttributeMaxDynamicSharedMemorySize, ATT_SMEM);

    dim3 ggrid(DIM / 128, SQ / 128);
    gemm_mma<1><<<ggrid, 256, 65536>>>(xh, xl, wqh, wql, bq, nullptr, qh, ql, nullptr);
    gemm_mma<1><<<ggrid, 256, 65536>>>(xh, xl, wkh, wkl, bk, nullptr, kh, kl, nullptr);
    gemm_mma<2><<<ggrid, 256, 65536>>>(xh, xl, wvh, wvl, bv, nullptr, nullptr, nullptr, vf);

    dim3 agrid(SQ / QT, NH);
    attn_mma<<<agrid, 128, ATT_SMEM>>>(qh, ql, kh, kl, vf, phase, oh, ol);

    gemm_mma<0><<<ggrid, 256, 65536>>>(oh, ol, woh, wol, bo, out, nullptr, nullptr, nullptr);
}

// round 16
// speedup vs baseline: 1.3090x; 1.0556x over previous
#include <cuda_runtime.h>
#include <cuda_bf16.h>
#include <cuda_fp16.h>
#include <stdint.h>

#define SQ   4096
#define DIM  1024
#define NH   16
#define HD   64
#define QT   128   // queries per attention block
#define KT   64

// Scratch (allocation-free rule: __device__ globals)
__device__ __nv_bfloat16 g_xh[SQ * DIM],  g_xl[SQ * DIM];
__device__ __nv_bfloat16 g_wqh[DIM * DIM], g_wql[DIM * DIM];
__device__ __nv_bfloat16 g_wkh[DIM * DIM], g_wkl[DIM * DIM];
__device__ __nv_bfloat16 g_wvh[DIM * DIM], g_wvl[DIM * DIM];
__device__ __nv_bfloat16 g_woh[DIM * DIM], g_wol[DIM * DIM];
__device__ float         g_q[SQ * DIM];      // tf32-rounded fp32
__device__ float         g_k[SQ * DIM];      // tf32-rounded fp32
__device__ __half        g_vf[SQ * DIM];
__device__ __nv_bfloat16 g_oh[SQ * DIM], g_ol[SQ * DIM];

// ---------------------------------------------------------------------------
// Helpers
// ---------------------------------------------------------------------------
__device__ __forceinline__ uint32_t smem_u32(const void* p) {
    uint32_t a;
    asm("{ .reg .u64 t; cvta.to.shared.u64 t, %1; cvt.u32.u64 %0, t; }"
        : "=r"(a) : "l"(p));
    return a;
}
#define SWZ(off)  ((off) ^ (((off) >> 3) & 0x70))   // 128B rows
#define SW64(off) ((off) ^ (((off) >> 3) & 0x30))   // 64B rows

#define CP16(dst, src) \
    asm volatile("cp.async.cg.shared.global [%0], [%1], 16;" :: "r"(dst), "l"(src))
#define CP_COMMIT() asm volatile("cp.async.commit_group;" ::: "memory")
#define CP_WAIT1()  asm volatile("cp.async.wait_group 1;" ::: "memory")

// tf32 cvt destination must be a .b32 register ("=r"), not .f32 ("=f").
__device__ __forceinline__ float to_tf32(float x) {
    uint32_t r;
    asm("cvt.rna.tf32.f32 %0, %1;" : "=r"(r) : "f"(x));
    return __uint_as_float(r);
}
__device__ __forceinline__ void mma_bf16(float* d, const uint32_t* a,
                                         uint32_t b0, uint32_t b1) {
    asm volatile(
        "mma.sync.aligned.m16n8k16.row.col.f32.bf16.bf16.f32 "
        "{%0,%1,%2,%3}, {%4,%5,%6,%7}, {%8,%9}, {%0,%1,%2,%3};"
        : "+f"(d[0]), "+f"(d[1]), "+f"(d[2]), "+f"(d[3])
        : "r"(a[0]), "r"(a[1]), "r"(a[2]), "r"(a[3]), "r"(b0), "r"(b1));
}
__device__ __forceinline__ void mma_fp16(float* d, const uint32_t* a,
                                         uint32_t b0, uint32_t b1) {
    asm volatile(
        "mma.sync.aligned.m16n8k16.row.col.f32.f16.f16.f32 "
        "{%0,%1,%2,%3}, {%4,%5,%6,%7}, {%8,%9}, {%0,%1,%2,%3};"
        : "+f"(d[0]), "+f"(d[1]), "+f"(d[2]), "+f"(d[3])
        : "r"(a[0]), "r"(a[1]), "r"(a[2]), "r"(a[3]), "r"(b0), "r"(b1));
}
__device__ __forceinline__ void mma_tf32(float* d, const uint32_t* a,
                                         uint32_t b0, uint32_t b1) {
    asm volatile(
        "mma.sync.aligned.m16n8k8.row.col.f32.tf32.tf32.f32 "
        "{%0,%1,%2,%3}, {%4,%5,%6,%7}, {%8,%9}, {%0,%1,%2,%3};"
        : "+f"(d[0]), "+f"(d[1]), "+f"(d[2]), "+f"(d[3])
        : "r"(a[0]), "r"(a[1]), "r"(a[2]), "r"(a[3]), "r"(b0), "r"(b1));
}
__device__ __forceinline__ void ldm_x4(uint32_t* r, uint32_t addr) {
    asm volatile("ldmatrix.sync.aligned.m8n8.x4.shared.b16 {%0,%1,%2,%3}, [%4];"
        : "=r"(r[0]), "=r"(r[1]), "=r"(r[2]), "=r"(r[3]) : "r"(addr));
}
__device__ __forceinline__ void ldm_x4_t(uint32_t* r, uint32_t addr) {
    asm volatile("ldmatrix.sync.aligned.m8n8.x4.trans.shared.b16 {%0,%1,%2,%3}, [%4];"
        : "=r"(r[0]), "=r"(r[1]), "=r"(r[2]), "=r"(r[3]) : "r"(addr));
}

// ---------------------------------------------------------------------------
// fp32 -> bf16 hi/lo split (elementwise)
// ---------------------------------------------------------------------------
__global__ void __launch_bounds__(256) split32(
    const float* __restrict__ in, __nv_bfloat16* __restrict__ hi,
    __nv_bfloat16* __restrict__ lo, int n)
{
    int i = (blockIdx.x * 256 + threadIdx.x) * 4;
    if (i >= n) return;
    float4 f = *(const float4*)(in + i);
    __nv_bfloat162 h0 = __floats2bfloat162_rn(f.x, f.y);
    __nv_bfloat162 h1 = __floats2bfloat162_rn(f.z, f.w);
    __nv_bfloat162 l0 = __floats2bfloat162_rn(f.x - __bfloat162float(h0.x),
                                              f.y - __bfloat162float(h0.y));
    __nv_bfloat162 l1 = __floats2bfloat162_rn(f.z - __bfloat162float(h1.x),
                                              f.w - __bfloat162float(h1.y));
    uint2 hv = {*(uint32_t*)&h0, *(uint32_t*)&h1};
    uint2 lv = {*(uint32_t*)&l0, *(uint32_t*)&l1};
    *(uint2*)(hi + i) = hv;
    *(uint2*)(lo + i) = lv;
}

// ---------------------------------------------------------------------------
// Split-bf16 tensor GEMM: C[M,N] = A @ B^T + bias.
// OUT_MODE: 0 fp32; 1 bf16 hi/lo; 2 fp16; 3 tf32-rounded fp32.
// ---------------------------------------------------------------------------
#define GS_STAGE 32768

template<int OUT_MODE>
__global__ void __launch_bounds__(256, 1) gemm_mma(
    const __nv_bfloat16* __restrict__ Agh, const __nv_bfloat16* __restrict__ Agl,
    const __nv_bfloat16* __restrict__ Bgh, const __nv_bfloat16* __restrict__ Bgl,
    const float* __restrict__ bias, float* __restrict__ C,
    __nv_bfloat16* __restrict__ Chi, __nv_bfloat16* __restrict__ Clo,
    __half* __restrict__ Cf16)
{
    extern __shared__ char sm[];
    const uint32_t smb = smem_u32(sm);
    const int tid = threadIdx.x, lane = tid & 31, warp = tid >> 5;
    const int bm = blockIdx.y * 128, bn = blockIdx.x * 128;
    const int wm = (warp >> 2) * 64, wn = (warp & 3) * 32;

    const int buf = tid >> 6, lrow = tid & 63;
    const __nv_bfloat16* gp[4] = {Agh, Agl, Bgh, Bgl};
    const int rbase = (buf < 2 ? bm : bn) + lrow;
    const __nv_bfloat16* src0 = gp[buf] + (size_t)rbase * DIM;
    const __nv_bfloat16* src1 = gp[buf] + (size_t)(rbase + 64) * DIM;

    float acc[4][4][4];
#pragma unroll
    for (int a = 0; a < 4; a++)
#pragma unroll
        for (int b = 0; b < 4; b++)
#pragma unroll
            for (int c = 0; c < 4; c++) acc[a][b][c] = 0.f;

    {
        uint32_t db = smb + buf * 8192;
#pragma unroll
        for (int i = 0; i < 4; i++) {
            CP16(db + SW64((uint32_t)(lrow * 64 + i * 16)),        src0 + i * 8);
            CP16(db + SW64((uint32_t)((lrow + 64) * 64 + i * 16)), src1 + i * 8);
        }
    }
    CP_COMMIT();

    for (int kt = 0; kt < 32; kt++) {
        if (kt + 1 < 32) {
            uint32_t db = smb + ((kt + 1) & 1) * GS_STAGE + buf * 8192;
            const __nv_bfloat16* s0 = src0 + (kt + 1) * 32;
            const __nv_bfloat16* s1 = src1 + (kt + 1) * 32;
#pragma unroll
            for (int i = 0; i < 4; i++) {
                CP16(db + SW64((uint32_t)(lrow * 64 + i * 16)),        s0 + i * 8);
                CP16(db + SW64((uint32_t)((lrow + 64) * 64 + i * 16)), s1 + i * 8);
            }
        }
        CP_COMMIT();
        CP_WAIT1();
        __syncthreads();

        const uint32_t sb = smb + (kt & 1) * GS_STAGE;
#pragma unroll
        for (int kk = 0; kk < 2; kk++) {
            uint32_t ah[4][4], al[4][4];
#pragma unroll
            for (int mf = 0; mf < 4; mf++) {
                uint32_t off = SW64((uint32_t)((wm + mf * 16 + (lane & 15)) * 64
                                    + kk * 32 + (lane >> 4) * 16));
                ldm_x4(ah[mf], sb + off);
                ldm_x4(al[mf], sb + 8192 + off);
            }
#pragma unroll
            for (int nf = 0; nf < 2; nf++) {
                uint32_t bh[4], bl[4];
                uint32_t off = SW64((uint32_t)((wn + nf * 16 + ((lane >> 4) << 3)
                                    + (lane & 7)) * 64 + kk * 32
                                    + ((lane >> 3) & 1) * 16));
                ldm_x4(bh, sb + 16384 + off);
                ldm_x4(bl, sb + 24576 + off);
#pragma unroll
                for (int mf = 0; mf < 4; mf++) {
                    mma_bf16(acc[mf][2*nf],   ah[mf], bh[0], bh[1]);
                    mma_bf16(acc[mf][2*nf],   ah[mf], bl[0], bl[1]);
                    mma_bf16(acc[mf][2*nf],   al[mf], bh[0], bh[1]);
                    mma_bf16(acc[mf][2*nf+1], ah[mf], bh[2], bh[3]);
                    mma_bf16(acc[mf][2*nf+1], ah[mf], bl[2], bl[3]);
                    mma_bf16(acc[mf][2*nf+1], al[mf], bh[2], bh[3]);
                }
            }
        }
        __syncthreads();
    }

#pragma unroll
    for (int mf = 0; mf < 4; mf++) {
        int r0 = bm + wm + mf * 16 + (lane >> 2);
#pragma unroll
        for (int nf8 = 0; nf8 < 4; nf8++) {
            int c = bn + wn + nf8 * 8 + (lane & 3) * 2;
            float b0 = bias[c], b1 = bias[c + 1];
            float v0 = acc[mf][nf8][0] + b0, v1 = acc[mf][nf8][1] + b1;
            float v2 = acc[mf][nf8][2] + b0, v3 = acc[mf][nf8][3] + b1;
            if (OUT_MODE == 1) {
                __nv_bfloat162 h0 = __floats2bfloat162_rn(v0, v1);
                __nv_bfloat162 l0 = __floats2bfloat162_rn(v0 - __bfloat162float(h0.x),
                                                          v1 - __bfloat162float(h0.y));
                __nv_bfloat162 h1 = __floats2bfloat162_rn(v2, v3);
                __nv_bfloat162 l1 = __floats2bfloat162_rn(v2 - __bfloat162float(h1.x),
                                                          v3 - __bfloat162float(h1.y));
                *(uint32_t*)&Chi[(size_t)r0 * DIM + c]       = *(uint32_t*)&h0;
                *(uint32_t*)&Clo[(size_t)r0 * DIM + c]       = *(uint32_t*)&l0;
                *(uint32_t*)&Chi[(size_t)(r0 + 8) * DIM + c] = *(uint32_t*)&h1;
                *(uint32_t*)&Clo[(size_t)(r0 + 8) * DIM + c] = *(uint32_t*)&l1;
            } else if (OUT_MODE == 2) {
                __half2 f0 = __floats2half2_rn(v0, v1);
                __half2 f1 = __floats2half2_rn(v2, v3);
                *(uint32_t*)&Cf16[(size_t)r0 * DIM + c]       = *(uint32_t*)&f0;
                *(uint32_t*)&Cf16[(size_t)(r0 + 8) * DIM + c] = *(uint32_t*)&f1;
            } else if (OUT_MODE == 3) {
                float2 w0 = {to_tf32(v0), to_tf32(v1)};
                float2 w1 = {to_tf32(v2), to_tf32(v3)};
                *(float2*)&C[(size_t)r0 * DIM + c]       = w0;
                *(float2*)&C[(size_t)(r0 + 8) * DIM + c] = w1;
            } else {
                float2 w0 = {v0, v1}, w1 = {v2, v3};
                *(float2*)&C[(size_t)r0 * DIM + c]       = w0;
                *(float2*)&C[(size_t)(r0 + 8) * DIM + c] = w1;
            }
        }
    }
}

// ---------------------------------------------------------------------------
// Attention: QK single tf32 (k8 chunks), PV fp16 single.
// QT=128, 4 warps x 32 q-rows; 2 CTAs/SM.
// smem: Qa 16K + Qb 16K + 2 KV stages x (Ka 8K + Kb 8K + V 8K) = 80KB.
// Q/K fp32 tiles stored as two 128B-row buffers (cols 0-31 / 32-63).
// ---------------------------------------------------------------------------
#define SM_QA   0
#define SM_QB   16384
#define SM_KV0  32768
#define KV_STAGE 24576
#define ATT_SMEM (32768 + 2 * KV_STAGE)   // 81920

__global__ void __launch_bounds__(128, 2) attn_mma(
    const float* __restrict__ Qf, const float* __restrict__ Kf,
    const __half* __restrict__ Vf,
    const float* __restrict__ phase,
    __nv_bfloat16* __restrict__ Oh, __nv_bfloat16* __restrict__ Ol)
{
    extern __shared__ char sm[];
    const uint32_t smb = smem_u32(sm);
    const int tid  = threadIdx.x;
    const int lane = tid & 31;
    const int warp = tid >> 5;           // 0..3
    const int h  = blockIdx.y;
    const int qb = blockIdx.x * QT;
    const int m0 = warp * 32;            // warp owns 32 q-rows (2 m-frags)
    const float ph = phase[h];

    // KV loader: warps 0,1 -> K fp32 rows (1 row = 256B -> Ka+Kb); warps 2,3 -> V
    const int grp = tid >> 5, lrow = tid & 31;
    const int krow_ld = grp * 32 + lrow;          // valid for grp<2: rows 0..63
    const int vrow_ld = (grp - 2) * 32 + lrow;    // valid for grp>=2

    // prologue: prefetch KV tile 0
    {
        uint32_t db = smb + SM_KV0;
        if (grp < 2) {
            const float* s0 = Kf + (size_t)krow_ld * DIM + h * HD;
#pragma unroll
            for (int i = 0; i < 8; i++) {
                CP16(db + SWZ((uint32_t)(krow_ld * 128 + i * 16)),        s0 + i * 4);
                CP16(db + 8192 + SWZ((uint32_t)(krow_ld * 128 + i * 16)), s0 + 32 + i * 4);
            }
        } else {
            const __half* sv = Vf + (size_t)vrow_ld * DIM + h * HD;
#pragma unroll
            for (int i = 0; i < 8; i++)
                CP16(db + 16384 + SWZ((uint32_t)(vrow_ld * 128 + i * 16)), sv + i * 8);
        }
    }
    CP_COMMIT();

    // stage Q fp32 tile: thread stages row tid (256B -> Qa first 128B, Qb second)
    {
        const int row = tid;
        const uint4* s4 = (const uint4*)(Qf + (size_t)(qb + row) * DIM + h * HD);
#pragma unroll
        for (int i = 0; i < 8; i++) {
            uint32_t off = SWZ((uint32_t)(row * 128 + i * 16));
            *(uint4*)(sm + SM_QA + off) = s4[i];
            *(uint4*)(sm + SM_QB + off) = s4[i + 8];
        }
    }
    __syncthreads();

    // persist Q tf32 A-fragments: 2 m-frags x 8 k8-chunks x 4 regs
    uint32_t qf[2][8][4];
    {
        const uint32_t qcol = (uint32_t)((lane >> 4) * 16);
#pragma unroll
        for (int mf = 0; mf < 2; mf++) {
            const uint32_t qrow = (uint32_t)(m0 + mf * 16 + (lane & 15));
#pragma unroll
            for (int c = 0; c < 8; c++) {
                uint32_t base = (c < 4) ? SM_QA : SM_QB;
                uint32_t off = SWZ(qrow * 128 + (c & 3) * 32 + qcol);
                ldm_x4(qf[mf][c], smb + base + off);
            }
        }
    }

    const uint32_t krow = (uint32_t)(((lane >> 4) << 3) + (lane & 7));
    const uint32_t kcol = (uint32_t)(((lane >> 3) & 1) * 16);
    const uint32_t vrow = (uint32_t)((((lane >> 3) & 1) << 3) + (lane & 7));
    const uint32_t vcol = (uint32_t)((lane >> 4) * 16);

    float o[2][8][4];
#pragma unroll
    for (int mf = 0; mf < 2; mf++)
#pragma unroll
        for (int n = 0; n < 8; n++)
#pragma unroll
            for (int e = 0; e < 4; e++) o[mf][n][e] = 0.f;
    float lsum[2][2] = {{0.f, 0.f}, {0.f, 0.f}};

    for (int t = 0; t < SQ / KT; t++) {
        // prefetch next KV tile into other stage
        if (t + 1 < SQ / KT) {
            uint32_t db = smb + SM_KV0 + ((t + 1) & 1) * KV_STAGE;
            const size_t roff = (size_t)(t + 1) * KT * DIM;
            if (grp < 2) {
                const float* s0 = Kf + roff + (size_t)krow_ld * DIM + h * HD;
#pragma unroll
                for (int i = 0; i < 8; i++) {
                    CP16(db + SWZ((uint32_t)(krow_ld * 128 + i * 16)),        s0 + i * 4);
                    CP16(db + 8192 + SWZ((uint32_t)(krow_ld * 128 + i * 16)), s0 + 32 + i * 4);
                }
            } else {
                const __half* sv = Vf + roff + (size_t)vrow_ld * DIM + h * HD;
#pragma unroll
                for (int i = 0; i < 8; i++)
                    CP16(db + 16384 + SWZ((uint32_t)(vrow_ld * 128 + i * 16)), sv + i * 8);
            }
        }
        CP_COMMIT();
        CP_WAIT1();
        __syncthreads();

        const uint32_t kvb = smb + SM_KV0 + (t & 1) * KV_STAGE;

        // ---- S = Q K^T (tf32, 8 k8-chunks) ----
        float s[2][8][4];
#pragma unroll
        for (int mf = 0; mf < 2; mf++)
#pragma unroll
            for (int n = 0; n < 8; n++)
#pragma unroll
                for (int e = 0; e < 4; e++) s[mf][n][e] = 0.f;

#pragma unroll
        for (int c = 0; c < 8; c++) {
            const uint32_t kbuf = kvb + ((c < 4) ? 0u : 8192u);
            const uint32_t colb = (uint32_t)((c & 3) * 32);
#pragma unroll
            for (int np = 0; np < 4; np++) {
                uint32_t bk[4];
                ldm_x4(bk, kbuf + SWZ((np * 16 + krow) * 128 + colb + kcol));
#pragma unroll
                for (int mf = 0; mf < 2; mf++) {
                    mma_tf32(s[mf][2*np],   qf[mf][c], bk[0], bk[1]);
                    mma_tf32(s[mf][2*np+1], qf[mf][c], bk[2], bk[3]);
                }
            }
        }

        // ---- modulation + exp(. - 4) ----
#pragma unroll
        for (int mf = 0; mf < 2; mf++)
#pragma unroll
            for (int n = 0; n < 8; n++) {
#pragma unroll
                for (int e = 0; e < 4; e++) {
                    float sc = s[mf][n][e] * 0.125f;
                    float m  = sc * (1.f + 0.1f * __cosf(ph * sc));
                    s[mf][n][e] = __expf(m - 4.f);
                }
                lsum[mf][0] += s[mf][n][0] + s[mf][n][1];
                lsum[mf][1] += s[mf][n][2] + s[mf][n][3];
            }

        // ---- O += P V (fp16 single product) ----
#pragma unroll
        for (int kk = 0; kk < 4; kk++) {
            const int t0 = 2 * kk, t1 = 2 * kk + 1;
            uint32_t ah[2][4];
#pragma unroll
            for (int mf = 0; mf < 2; mf++) {
                __half2 p0 = __floats2half2_rn(s[mf][t0][0], s[mf][t0][1]);
                __half2 p1 = __floats2half2_rn(s[mf][t0][2], s[mf][t0][3]);
                __half2 p2 = __floats2half2_rn(s[mf][t1][0], s[mf][t1][1]);
                __half2 p3 = __floats2half2_rn(s[mf][t1][2], s[mf][t1][3]);
                ah[mf][0] = *(uint32_t*)&p0;
                ah[mf][1] = *(uint32_t*)&p1;
                ah[mf][2] = *(uint32_t*)&p2;
                ah[mf][3] = *(uint32_t*)&p3;
            }
#pragma unroll
            for (int dp = 0; dp < 4; dp++) {
                uint32_t bv[4];
                uint32_t off = SWZ((kk * 16 + vrow) * 128 + dp * 32 + vcol);
                ldm_x4_t(bv, kvb + 16384 + off);
#pragma unroll
                for (int mf = 0; mf < 2; mf++) {
                    mma_fp16(o[mf][2*dp],   ah[mf], bv[0], bv[1]);
                    mma_fp16(o[mf][2*dp+1], ah[mf], bv[2], bv[3]);
                }
            }
        }
        __syncthreads();
    }

    // ---- finalize: l-reduce, scale, write split bf16 ----
#pragma unroll
    for (int mf = 0; mf < 2; mf++) {
        float l0 = lsum[mf][0], l8 = lsum[mf][1];
        l0 += __shfl_xor_sync(0xffffffffu, l0, 1);
        l0 += __shfl_xor_sync(0xffffffffu, l0, 2);
        l8 += __shfl_xor_sync(0xffffffffu, l8, 1);
        l8 += __shfl_xor_sync(0xffffffffu, l8, 2);
        const float inv0 = 1.f / l0;
        const float inv8 = 1.f / l8;

        const int row0 = qb + m0 + mf * 16 + (lane >> 2);
        const int colb = h * HD + (lane & 3) * 2;
#pragma unroll
        for (int n = 0; n < 8; n++) {
            float a0 = o[mf][n][0] * inv0, a1 = o[mf][n][1] * inv0;
            float b0 = o[mf][n][2] * inv8, b1 = o[mf][n][3] * inv8;
            __nv_bfloat162 h0 = __floats2bfloat162_rn(a0, a1);
            __nv_bfloat162 l0p = __floats2bfloat162_rn(a0 - __bfloat162float(h0.x),
                                                       a1 - __bfloat162float(h0.y));
            __nv_bfloat162 h1 = __floats2bfloat162_rn(b0, b1);
            __nv_bfloat162 l1p = __floats2bfloat162_rn(b0 - __bfloat162float(h1.x),
                                                       b1 - __bfloat162float(h1.y));
            size_t i0 = (size_t)row0 * DIM + colb + n * 8;
            size_t i1 = (size_t)(row0 + 8) * DIM + colb + n * 8;
            *(uint32_t*)&Oh[i0] = *(uint32_t*)&h0;
            *(uint32_t*)&Ol[i0] = *(uint32_t*)&l0p;
            *(uint32_t*)&Oh[i1] = *(uint32_t*)&h1;
            *(uint32_t*)&Ol[i1] = *(uint32_t*)&l1p;
        }
    }
}

// ---------------------------------------------------------------------------
extern "C" void kernel_launch(void* const* d_in, const int* in_sizes, int n_in,
                              void* d_out, int out_size)
{
    const float* x     = (const float*)d_in[0];
    const float* wq    = (const float*)d_in[1];
    const float* bq    = (const float*)d_in[2];
    const float* wk    = (const float*)d_in[3];
    const float* bk    = (const float*)d_in[4];
    const float* wv    = (const float*)d_in[5];
    const float* bv    = (const float*)d_in[6];
    const float* wo    = (const float*)d_in[7];
    const float* bo    = (const float*)d_in[8];
    const float* phase = (const float*)d_in[9];
    float* out = (float*)d_out;

    __nv_bfloat16 *xh, *xl, *wqh, *wql, *wkh, *wkl, *wvh, *wvl, *woh, *wol;
    __nv_bfloat16 *oh, *ol;
    float *qf, *kf;
    __half *vf;
    cudaGetSymbolAddress((void**)&xh,  g_xh);  cudaGetSymbolAddress((void**)&xl,  g_xl);
    cudaGetSymbolAddress((void**)&wqh, g_wqh); cudaGetSymbolAddress((void**)&wql, g_wql);
    cudaGetSymbolAddress((void**)&wkh, g_wkh); cudaGetSymbolAddress((void**)&wkl, g_wkl);
    cudaGetSymbolAddress((void**)&wvh, g_wvh); cudaGetSymbolAddress((void**)&wvl, g_wvl);
    cudaGetSymbolAddress((void**)&woh, g_woh); cudaGetSymbolAddress((void**)&wol, g_wol);
    cudaGetSymbolAddress((void**)&qf, g_q);  cudaGetSymbolAddress((void**)&kf, g_k);
    cudaGetSymbolAddress((void**)&vf, g_vf);
    cudaGetSymbolAddress((void**)&oh, g_oh); cudaGetSymbolAddress((void**)&ol, g_ol);

    // splits
    split32<<<SQ * DIM / 1024, 256>>>(x, xh, xl, SQ * DIM);
    split32<<<DIM * DIM / 1024, 256>>>(wq, wqh, wql, DIM * DIM);
    split32<<<DIM * DIM / 1024, 256>>>(wk, wkh, wkl, DIM * DIM);
    split32<<<DIM * DIM / 1024, 256>>>(wv, wvh, wvl, DIM * DIM);
    split32<<<DIM * DIM / 1024, 256>>>(wo, woh, wol, DIM * DIM);

    cudaFuncSetAttribute(gemm_mma<0>, cudaFuncAttributeMaxDynamicSharedMemorySize, 65536);
    cudaFuncSetAttribute(gemm_mma<2>, cudaFuncAttributeMaxDynamicSharedMemorySize, 65536);
    cudaFuncSetAttribute(gemm_mma<3>, cudaFuncAttributeMaxDynamicSharedMemorySize, 65536);
    cudaFuncSetAttribute(attn_mma,    cudaFuncAttributeMaxDynamicSharedMemorySize, ATT_SMEM);

    dim3 ggrid(DIM / 128, SQ / 128);
    gemm_mma<3><<<ggrid, 256, 65536>>>(xh, xl, wqh, wql, bq, qf, nullptr, nullptr, nullptr);
    gemm_mma<3><<<ggrid, 256, 65536>>>(xh, xl, wkh, wkl, bk, kf, nullptr, nullptr, nullptr);
    gemm_mma<2><<<ggrid, 256, 65536>>>(xh, xl, wvh, wvl, bv, nullptr, nullptr, nullptr, vf);

    dim3 agrid(SQ / QT, NH);
    attn_mma<<<agrid, 128, ATT_SMEM>>>(qf, kf, vf, phase, oh, ol);

    gemm_mma<0><<<ggrid, 256, 65536>>>(oh, ol, woh, wol, bo, out, nullptr, nullptr, nullptr);
}

// round 17
// speedup vs baseline: 1.3685x; 1.0455x over previous
#include <cuda_runtime.h>
#include <cuda_bf16.h>
#include <cuda_fp16.h>
#include <stdint.h>

#define SQ   4096
#define DIM  1024
#define NH   16
#define HD   64
#define QT   128   // queries per attention block
#define KT   64

// Scratch (allocation-free rule: __device__ globals)
__device__ float  g_x[SQ * DIM];                    // tf32-rounded x
__device__ float  g_wq[DIM * DIM], g_wk[DIM * DIM]; // tf32-rounded weights
__device__ float  g_wv[DIM * DIM], g_wo[DIM * DIM];
__device__ float  g_q[SQ * DIM];                    // tf32-rounded Q
__device__ float  g_k[SQ * DIM];                    // tf32-rounded K
__device__ __half g_vf[SQ * DIM];                   // fp16 V
__device__ float  g_o[SQ * DIM];                    // tf32-rounded attention out

// ---------------------------------------------------------------------------
// Helpers
// ---------------------------------------------------------------------------
__device__ __forceinline__ uint32_t smem_u32(const void* p) {
    uint32_t a;
    asm("{ .reg .u64 t; cvta.to.shared.u64 t, %1; cvt.u32.u64 %0, t; }"
        : "=r"(a) : "l"(p));
    return a;
}
#define SWZ(off)  ((off) ^ (((off) >> 3) & 0x70))   // 128B rows

#define CP16(dst, src) \
    asm volatile("cp.async.cg.shared.global [%0], [%1], 16;" :: "r"(dst), "l"(src))
#define CP_COMMIT() asm volatile("cp.async.commit_group;" ::: "memory")
#define CP_WAIT1()  asm volatile("cp.async.wait_group 1;" ::: "memory")

// tf32 cvt destination must be a .b32 register ("=r").
__device__ __forceinline__ float to_tf32(float x) {
    uint32_t r;
    asm("cvt.rna.tf32.f32 %0, %1;" : "=r"(r) : "f"(x));
    return __uint_as_float(r);
}
__device__ __forceinline__ void mma_fp16(float* d, const uint32_t* a,
                                         uint32_t b0, uint32_t b1) {
    asm volatile(
        "mma.sync.aligned.m16n8k16.row.col.f32.f16.f16.f32 "
        "{%0,%1,%2,%3}, {%4,%5,%6,%7}, {%8,%9}, {%0,%1,%2,%3};"
        : "+f"(d[0]), "+f"(d[1]), "+f"(d[2]), "+f"(d[3])
        : "r"(a[0]), "r"(a[1]), "r"(a[2]), "r"(a[3]), "r"(b0), "r"(b1));
}
__device__ __forceinline__ void mma_tf32(float* d, const uint32_t* a,
                                         uint32_t b0, uint32_t b1) {
    asm volatile(
        "mma.sync.aligned.m16n8k8.row.col.f32.tf32.tf32.f32 "
        "{%0,%1,%2,%3}, {%4,%5,%6,%7}, {%8,%9}, {%0,%1,%2,%3};"
        : "+f"(d[0]), "+f"(d[1]), "+f"(d[2]), "+f"(d[3])
        : "r"(a[0]), "r"(a[1]), "r"(a[2]), "r"(a[3]), "r"(b0), "r"(b1));
}
__device__ __forceinline__ void ldm_x4(uint32_t* r, uint32_t addr) {
    asm volatile("ldmatrix.sync.aligned.m8n8.x4.shared.b16 {%0,%1,%2,%3}, [%4];"
        : "=r"(r[0]), "=r"(r[1]), "=r"(r[2]), "=r"(r[3]) : "r"(addr));
}
__device__ __forceinline__ void ldm_x4_t(uint32_t* r, uint32_t addr) {
    asm volatile("ldmatrix.sync.aligned.m8n8.x4.trans.shared.b16 {%0,%1,%2,%3}, [%4];"
        : "=r"(r[0]), "=r"(r[1]), "=r"(r[2]), "=r"(r[3]) : "r"(addr));
}

// ---------------------------------------------------------------------------
// fp32 -> tf32-rounded fp32 (elementwise; rna is unbiased — REQUIRED, since
// raw-fp32 truncation bias accumulates linearly over K=1024 sums)
// ---------------------------------------------------------------------------
__global__ void __launch_bounds__(256) round32(
    const float* __restrict__ in, float* __restrict__ outp, int n)
{
    int i = (blockIdx.x * 256 + threadIdx.x) * 4;
    if (i >= n) return;
    float4 f = *(const float4*)(in + i);
    float4 r = {to_tf32(f.x), to_tf32(f.y), to_tf32(f.z), to_tf32(f.w)};
    *(float4*)(outp + i) = r;
}

// ---------------------------------------------------------------------------
// tf32 tensor GEMM: C[M,N] = A @ B^T + bias; A,B tf32-rounded fp32 row-major.
// BM=BN=128, k-step 32 (128B rows), cp.async double buffer (2 x 32KB).
// 256 threads = 8 warps (2m x 4n), warp tile 64x32.
// OUT_MODE: 0 fp32; 2 fp16; 3 tf32-rounded fp32.
// ---------------------------------------------------------------------------
#define GS_STAGE 32768

template<int OUT_MODE>
__global__ void __launch_bounds__(256, 1) gemm_tf32(
    const float* __restrict__ Ag, const float* __restrict__ Bg,
    const float* __restrict__ bias, float* __restrict__ C,
    __half* __restrict__ Cf16)
{
    extern __shared__ char sm[];
    const uint32_t smb = smem_u32(sm);
    const int tid = threadIdx.x, lane = tid & 31, warp = tid >> 5;
    const int bm = blockIdx.y * 128, bn = blockIdx.x * 128;
    const int wm = (warp >> 2) * 64, wn = (warp & 3) * 32;

    // loader role: buf 0 -> A rows, buf 1 -> B rows; 128 threads per buf
    const int buf = tid >> 7, lrow = tid & 127;
    const float* src = (buf ? Bg + (size_t)(bn + lrow) * DIM
                            : Ag + (size_t)(bm + lrow) * DIM);

    float acc[4][4][4];
#pragma unroll
    for (int a = 0; a < 4; a++)
#pragma unroll
        for (int b = 0; b < 4; b++)
#pragma unroll
            for (int c = 0; c < 4; c++) acc[a][b][c] = 0.f;

    // prologue: stage 0 (k-cols 0..31 = 128B)
    {
        uint32_t db = smb + buf * 16384;
#pragma unroll
        for (int i = 0; i < 8; i++)
            CP16(db + SWZ((uint32_t)(lrow * 128 + i * 16)), src + i * 4);
    }
    CP_COMMIT();

    const uint32_t krow = (uint32_t)(((lane >> 4) << 3) + (lane & 7));
    const uint32_t kcol = (uint32_t)(((lane >> 3) & 1) * 16);

    for (int kt = 0; kt < 32; kt++) {
        if (kt + 1 < 32) {
            uint32_t db = smb + ((kt + 1) & 1) * GS_STAGE + buf * 16384;
            const float* s = src + (kt + 1) * 32;
#pragma unroll
            for (int i = 0; i < 8; i++)
                CP16(db + SWZ((uint32_t)(lrow * 128 + i * 16)), s + i * 4);
        }
        CP_COMMIT();
        CP_WAIT1();
        __syncthreads();

        const uint32_t sb = smb + (kt & 1) * GS_STAGE;
#pragma unroll
        for (int c = 0; c < 4; c++) {       // four k8 chunks in this k32 step
            uint32_t af[4][4];
#pragma unroll
            for (int mf = 0; mf < 4; mf++) {
                uint32_t off = SWZ((uint32_t)((wm + mf * 16 + (lane & 15)) * 128
                                    + c * 32 + (lane >> 4) * 16));
                ldm_x4(af[mf], sb + off);
            }
#pragma unroll
            for (int np = 0; np < 2; np++) {  // two n16 groups = four n8 tiles
                uint32_t bk[4];
                uint32_t off = SWZ((uint32_t)((wn + np * 16 + krow) * 128
                                    + c * 32 + kcol));
                ldm_x4(bk, sb + 16384 + off);
#pragma unroll
                for (int mf = 0; mf < 4; mf++) {
                    mma_tf32(acc[mf][2*np],   af[mf], bk[0], bk[1]);
                    mma_tf32(acc[mf][2*np+1], af[mf], bk[2], bk[3]);
                }
            }
        }
        __syncthreads();
    }

    // epilogue
#pragma unroll
    for (int mf = 0; mf < 4; mf++) {
        int r0 = bm + wm + mf * 16 + (lane >> 2);
#pragma unroll
        for (int nf8 = 0; nf8 < 4; nf8++) {
            int c = bn + wn + nf8 * 8 + (lane & 3) * 2;
            float b0 = bias[c], b1 = bias[c + 1];
            float v0 = acc[mf][nf8][0] + b0, v1 = acc[mf][nf8][1] + b1;
            float v2 = acc[mf][nf8][2] + b0, v3 = acc[mf][nf8][3] + b1;
            if (OUT_MODE == 2) {
                __half2 f0 = __floats2half2_rn(v0, v1);
                __half2 f1 = __floats2half2_rn(v2, v3);
                *(uint32_t*)&Cf16[(size_t)r0 * DIM + c]       = *(uint32_t*)&f0;
                *(uint32_t*)&Cf16[(size_t)(r0 + 8) * DIM + c] = *(uint32_t*)&f1;
            } else if (OUT_MODE == 3) {
                float2 w0 = {to_tf32(v0), to_tf32(v1)};
                float2 w1 = {to_tf32(v2), to_tf32(v3)};
                *(float2*)&C[(size_t)r0 * DIM + c]       = w0;
                *(float2*)&C[(size_t)(r0 + 8) * DIM + c] = w1;
            } else {
                float2 w0 = {v0, v1}, w1 = {v2, v3};
                *(float2*)&C[(size_t)r0 * DIM + c]       = w0;
                *(float2*)&C[(size_t)(r0 + 8) * DIM + c] = w1;
            }
        }
    }
}

// ---------------------------------------------------------------------------
// Attention: QK single tf32 (k8 chunks), PV fp16 single.  (unchanged from R16
// except: output is tf32-rounded fp32 into g_o for the tf32 O-projection)
// QT=128, 4 warps x 32 q-rows; 2 CTAs/SM.
// smem: Qa 16K + Qb 16K + 2 KV stages x (Ka 8K + Kb 8K + V 8K) = 80KB.
// ---------------------------------------------------------------------------
#define SM_QA   0
#define SM_QB   16384
#define SM_KV0  32768
#define KV_STAGE 24576
#define ATT_SMEM (32768 + 2 * KV_STAGE)   // 81920

__global__ void __launch_bounds__(128, 2) attn_mma(
    const float* __restrict__ Qf, const float* __restrict__ Kf,
    const __half* __restrict__ Vf,
    const float* __restrict__ phase,
    float* __restrict__ O)
{
    extern __shared__ char sm[];
    const uint32_t smb = smem_u32(sm);
    const int tid  = threadIdx.x;
    const int lane = tid & 31;
    const int warp = tid >> 5;           // 0..3
    const int h  = blockIdx.y;
    const int qb = blockIdx.x * QT;
    const int m0 = warp * 32;            // warp owns 32 q-rows (2 m-frags)
    const float ph = phase[h];

    // KV loader: warps 0,1 -> K fp32 rows (1 row = 256B -> Ka+Kb); warps 2,3 -> V
    const int grp = tid >> 5, lrow = tid & 31;
    const int krow_ld = grp * 32 + lrow;
    const int vrow_ld = (grp - 2) * 32 + lrow;

    // prologue: prefetch KV tile 0
    {
        uint32_t db = smb + SM_KV0;
        if (grp < 2) {
            const float* s0 = Kf + (size_t)krow_ld * DIM + h * HD;
#pragma unroll
            for (int i = 0; i < 8; i++) {
                CP16(db + SWZ((uint32_t)(krow_ld * 128 + i * 16)),        s0 + i * 4);
                CP16(db + 8192 + SWZ((uint32_t)(krow_ld * 128 + i * 16)), s0 + 32 + i * 4);
            }
        } else {
            const __half* sv = Vf + (size_t)vrow_ld * DIM + h * HD;
#pragma unroll
            for (int i = 0; i < 8; i++)
                CP16(db + 16384 + SWZ((uint32_t)(vrow_ld * 128 + i * 16)), sv + i * 8);
        }
    }
    CP_COMMIT();

    // stage Q fp32 tile: thread stages row tid (256B -> Qa first 128B, Qb second)
    {
        const int row = tid;
        const uint4* s4 = (const uint4*)(Qf + (size_t)(qb + row) * DIM + h * HD);
#pragma unroll
        for (int i = 0; i < 8; i++) {
            uint32_t off = SWZ((uint32_t)(row * 128 + i * 16));
            *(uint4*)(sm + SM_QA + off) = s4[i];
            *(uint4*)(sm + SM_QB + off) = s4[i + 8];
        }
    }
    __syncthreads();

    // persist Q tf32 A-fragments: 2 m-frags x 8 k8-chunks x 4 regs
    uint32_t qf[2][8][4];
    {
        const uint32_t qcol = (uint32_t)((lane >> 4) * 16);
#pragma unroll
        for (int mf = 0; mf < 2; mf++) {
            const uint32_t qrow = (uint32_t)(m0 + mf * 16 + (lane & 15));
#pragma unroll
            for (int c = 0; c < 8; c++) {
                uint32_t base = (c < 4) ? SM_QA : SM_QB;
                uint32_t off = SWZ(qrow * 128 + (c & 3) * 32 + qcol);
                ldm_x4(qf[mf][c], smb + base + off);
            }
        }
    }

    const uint32_t krow = (uint32_t)(((lane >> 4) << 3) + (lane & 7));
    const uint32_t kcol = (uint32_t)(((lane >> 3) & 1) * 16);
    const uint32_t vrow = (uint32_t)((((lane >> 3) & 1) << 3) + (lane & 7));
    const uint32_t vcol = (uint32_t)((lane >> 4) * 16);

    float o[2][8][4];
#pragma unroll
    for (int mf = 0; mf < 2; mf++)
#pragma unroll
        for (int n = 0; n < 8; n++)
#pragma unroll
            for (int e = 0; e < 4; e++) o[mf][n][e] = 0.f;
    float lsum[2][2] = {{0.f, 0.f}, {0.f, 0.f}};

    for (int t = 0; t < SQ / KT; t++) {
        if (t + 1 < SQ / KT) {
            uint32_t db = smb + SM_KV0 + ((t + 1) & 1) * KV_STAGE;
            const size_t roff = (size_t)(t + 1) * KT * DIM;
            if (grp < 2) {
                const float* s0 = Kf + roff + (size_t)krow_ld * DIM + h * HD;
#pragma unroll
                for (int i = 0; i < 8; i++) {
                    CP16(db + SWZ((uint32_t)(krow_ld * 128 + i * 16)),        s0 + i * 4);
                    CP16(db + 8192 + SWZ((uint32_t)(krow_ld * 128 + i * 16)), s0 + 32 + i * 4);
                }
            } else {
                const __half* sv = Vf + roff + (size_t)vrow_ld * DIM + h * HD;
#pragma unroll
                for (int i = 0; i < 8; i++)
                    CP16(db + 16384 + SWZ((uint32_t)(vrow_ld * 128 + i * 16)), sv + i * 8);
            }
        }
        CP_COMMIT();
        CP_WAIT1();
        __syncthreads();

        const uint32_t kvb = smb + SM_KV0 + (t & 1) * KV_STAGE;

        // ---- S = Q K^T (tf32, 8 k8-chunks) ----
        float s[2][8][4];
#pragma unroll
        for (int mf = 0; mf < 2; mf++)
#pragma unroll
            for (int n = 0; n < 8; n++)
#pragma unroll
                for (int e = 0; e < 4; e++) s[mf][n][e] = 0.f;

#pragma unroll
        for (int c = 0; c < 8; c++) {
            const uint32_t kbuf = kvb + ((c < 4) ? 0u : 8192u);
            const uint32_t colb = (uint32_t)((c & 3) * 32);
#pragma unroll
            for (int np = 0; np < 4; np++) {
                uint32_t bk[4];
                ldm_x4(bk, kbuf + SWZ((np * 16 + krow) * 128 + colb + kcol));
#pragma unroll
                for (int mf = 0; mf < 2; mf++) {
                    mma_tf32(s[mf][2*np],   qf[mf][c], bk[0], bk[1]);
                    mma_tf32(s[mf][2*np+1], qf[mf][c], bk[2], bk[3]);
                }
            }
        }

        // ---- modulation + exp(. - 4) ----
#pragma unroll
        for (int mf = 0; mf < 2; mf++)
#pragma unroll
            for (int n = 0; n < 8; n++) {
#pragma unroll
                for (int e = 0; e < 4; e++) {
                    float sc = s[mf][n][e] * 0.125f;
                    float m  = sc * (1.f + 0.1f * __cosf(ph * sc));
                    s[mf][n][e] = __expf(m - 4.f);
                }
                lsum[mf][0] += s[mf][n][0] + s[mf][n][1];
                lsum[mf][1] += s[mf][n][2] + s[mf][n][3];
            }

        // ---- O += P V (fp16 single product) ----
#pragma unroll
        for (int kk = 0; kk < 4; kk++) {
            const int t0 = 2 * kk, t1 = 2 * kk + 1;
            uint32_t ah[2][4];
#pragma unroll
            for (int mf = 0; mf < 2; mf++) {
                __half2 p0 = __floats2half2_rn(s[mf][t0][0], s[mf][t0][1]);
                __half2 p1 = __floats2half2_rn(s[mf][t0][2], s[mf][t0][3]);
                __half2 p2 = __floats2half2_rn(s[mf][t1][0], s[mf][t1][1]);
                __half2 p3 = __floats2half2_rn(s[mf][t1][2], s[mf][t1][3]);
                ah[mf][0] = *(uint32_t*)&p0;
                ah[mf][1] = *(uint32_t*)&p1;
                ah[mf][2] = *(uint32_t*)&p2;
                ah[mf][3] = *(uint32_t*)&p3;
            }
#pragma unroll
            for (int dp = 0; dp < 4; dp++) {
                uint32_t bv[4];
                uint32_t off = SWZ((kk * 16 + vrow) * 128 + dp * 32 + vcol);
                ldm_x4_t(bv, kvb + 16384 + off);
#pragma unroll
                for (int mf = 0; mf < 2; mf++) {
                    mma_fp16(o[mf][2*dp],   ah[mf], bv[0], bv[1]);
                    mma_fp16(o[mf][2*dp+1], ah[mf], bv[2], bv[3]);
                }
            }
        }
        __syncthreads();
    }

    // ---- finalize: l-reduce, scale, write tf32-rounded fp32 ----
#pragma unroll
    for (int mf = 0; mf < 2; mf++) {
        float l0 = lsum[mf][0], l8 = lsum[mf][1];
        l0 += __shfl_xor_sync(0xffffffffu, l0, 1);
        l0 += __shfl_xor_sync(0xffffffffu, l0, 2);
        l8 += __shfl_xor_sync(0xffffffffu, l8, 1);
        l8 += __shfl_xor_sync(0xffffffffu, l8, 2);
        const float inv0 = 1.f / l0;
        const float inv8 = 1.f / l8;

        const int row0 = qb + m0 + mf * 16 + (lane >> 2);
        const int colb = h * HD + (lane & 3) * 2;
#pragma unroll
        for (int n = 0; n < 8; n++) {
            float2 w0 = {to_tf32(o[mf][n][0] * inv0), to_tf32(o[mf][n][1] * inv0)};
            float2 w1 = {to_tf32(o[mf][n][2] * inv8), to_tf32(o[mf][n][3] * inv8)};
            *(float2*)&O[(size_t)row0 * DIM + colb + n * 8]       = w0;
            *(float2*)&O[(size_t)(row0 + 8) * DIM + colb + n * 8] = w1;
        }
    }
}

// ---------------------------------------------------------------------------
extern "C" void kernel_launch(void* const* d_in, const int* in_sizes, int n_in,
                              void* d_out, int out_size)
{
    const float* x     = (const float*)d_in[0];
    const float* wq    = (const float*)d_in[1];
    const float* bq    = (const float*)d_in[2];
    const float* wk    = (const float*)d_in[3];
    const float* bk    = (const float*)d_in[4];
    const float* wv    = (const float*)d_in[5];
    const float* bv    = (const float*)d_in[6];
    const float* wo    = (const float*)d_in[7];
    const float* bo    = (const float*)d_in[8];
    const float* phase = (const float*)d_in[9];
    float* out = (float*)d_out;

    float *xr, *wqr, *wkr, *wvr, *wor, *qf, *kf, *of;
    __half *vf;
    cudaGetSymbolAddress((void**)&xr,  g_x);
    cudaGetSymbolAddress((void**)&wqr, g_wq);
    cudaGetSymbolAddress((void**)&wkr, g_wk);
    cudaGetSymbolAddress((void**)&wvr, g_wv);
    cudaGetSymbolAddress((void**)&wor, g_wo);
    cudaGetSymbolAddress((void**)&qf, g_q);
    cudaGetSymbolAddress((void**)&kf, g_k);
    cudaGetSymbolAddress((void**)&vf, g_vf);
    cudaGetSymbolAddress((void**)&of, g_o);

    // tf32 rounding pre-passes (rna: unbiased)
    round32<<<SQ * DIM / 1024, 256>>>(x, xr, SQ * DIM);
    round32<<<DIM * DIM / 1024, 256>>>(wq, wqr, DIM * DIM);
    round32<<<DIM * DIM / 1024, 256>>>(wk, wkr, DIM * DIM);
    round32<<<DIM * DIM / 1024, 256>>>(wv, wvr, DIM * DIM);
    round32<<<DIM * DIM / 1024, 256>>>(wo, wor, DIM * DIM);

    cudaFuncSetAttribute(gemm_tf32<0>, cudaFuncAttributeMaxDynamicSharedMemorySize, 65536);
    cudaFuncSetAttribute(gemm_tf32<2>, cudaFuncAttributeMaxDynamicSharedMemorySize, 65536);
    cudaFuncSetAttribute(gemm_tf32<3>, cudaFuncAttributeMaxDynamicSharedMemorySize, 65536);
    cudaFuncSetAttribute(attn_mma,     cudaFuncAttributeMaxDynamicSharedMemorySize, ATT_SMEM);

    dim3 ggrid(DIM / 128, SQ / 128);
    gemm_tf32<3><<<ggrid, 256, 65536>>>(xr, wqr, bq, qf, nullptr);
    gemm_tf32<3><<<ggrid, 256, 65536>>>(xr, wkr, bk, kf, nullptr);
    gemm_tf32<2><<<ggrid, 256, 65536>>>(xr, wvr, bv, nullptr, vf);

    dim3 agrid(SQ / QT, NH);
    attn_mma<<<agrid, 128, ATT_SMEM>>>(qf, kf, vf, phase, of);

    gemm_tf32<0><<<ggrid, 256, 65536>>>(of, wor, bo, out, nullptr);
}